// round 2
// baseline (speedup 1.0000x reference)
#include <cuda_runtime.h>
#include <cuda_bf16.h>
#include <math.h>

// ---------------- problem constants ----------------
#define BATCH 8
#define SEQ   1024
#define EMBED 512
#define BN    (BATCH*SEQ)          // 8192
#define HEADS 8
#define HD    32                   // diff-attn sub-head dim
#define VD    64                   // v head dim = 2*HD
#define EXPD  2048                 // 4*EMBED
#define LAMBDA_INIT 0.2f
#define EPS_LN 1e-5f

// ---------------- device scratch (static, no allocation) ----------------
__device__ float g_xn[(size_t)BN*EMBED];
__device__ float g_q [(size_t)BN*EMBED];
__device__ float g_k [(size_t)BN*EMBED];
__device__ float g_v [(size_t)BN*EMBED];
__device__ float g_ao[(size_t)BN*EMBED];
__device__ float g_a [(size_t)BN*EMBED];
__device__ float g_h [(size_t)BN*EMBED];
__device__ float g_z1[(size_t)BN*EXPD];
__device__ float g_z2[(size_t)BN*EXPD];

// ---------------- block reduction (128 threads) ----------------
__device__ __forceinline__ float block_sum128(float v) {
    __shared__ float sm[4];
    #pragma unroll
    for (int o = 16; o; o >>= 1) v += __shfl_xor_sync(0xffffffffu, v, o);
    if ((threadIdx.x & 31) == 0) sm[threadIdx.x >> 5] = v;
    __syncthreads();
    float t = sm[0] + sm[1] + sm[2] + sm[3];
    __syncthreads();
    return t;
}

// ---------------- generic LayerNorm: one row per block, 128 threads ----------------
template<int D>
__global__ __launch_bounds__(128) void ln_kernel(
    const float* __restrict__ in, const float* __restrict__ w,
    const float* __restrict__ b, float* __restrict__ out)
{
    constexpr int V = D / 512;   // float4 per thread (D=512 -> 1, D=2048 -> 4)
    const size_t base = (size_t)blockIdx.x * D;
    float4 xv[V];
    float s = 0.f;
    #pragma unroll
    for (int j = 0; j < V; j++) {
        xv[j] = *(const float4*)(in + base + (size_t)(j * 128 + threadIdx.x) * 4);
        s += xv[j].x + xv[j].y + xv[j].z + xv[j].w;
    }
    const float mu = block_sum128(s) * (1.f / D);
    float vs = 0.f;
    #pragma unroll
    for (int j = 0; j < V; j++) {
        float dx = xv[j].x - mu, dy = xv[j].y - mu, dz = xv[j].z - mu, dw = xv[j].w - mu;
        vs += dx*dx + dy*dy + dz*dz + dw*dw;
    }
    const float var = block_sum128(vs) * (1.f / D);
    const float rs = rsqrtf(var + EPS_LN);
    #pragma unroll
    for (int j = 0; j < V; j++) {
        int idx = (j * 128 + threadIdx.x) * 4;
        float4 wv = *(const float4*)(w + idx);
        float4 bv = *(const float4*)(b + idx);
        float4 o;
        o.x = (xv[j].x - mu) * rs * wv.x + bv.x;
        o.y = (xv[j].y - mu) * rs * wv.y + bv.y;
        o.z = (xv[j].z - mu) * rs * wv.z + bv.z;
        o.w = (xv[j].w - mu) * rs * wv.w + bv.w;
        *(float4*)(out + base + idx) = o;
    }
}

// ---------------- fused: h = LN(a)+x ; z = LN(h)  (D=512) ----------------
__global__ __launch_bounds__(128) void hz_kernel(
    const float* __restrict__ a, const float* __restrict__ x,
    const float* __restrict__ n2w, const float* __restrict__ n2b,
    const float* __restrict__ m1w, const float* __restrict__ m1b,
    float* __restrict__ h, float* __restrict__ z)
{
    const size_t base = (size_t)blockIdx.x * EMBED;
    const int t4 = threadIdx.x * 4;
    float4 av = *(const float4*)(a + base + t4);
    float4 xv = *(const float4*)(x + base + t4);

    float s = av.x + av.y + av.z + av.w;
    float mu = block_sum128(s) * (1.f / EMBED);
    float dx = av.x-mu, dy = av.y-mu, dz = av.z-mu, dw = av.w-mu;
    float var = block_sum128(dx*dx+dy*dy+dz*dz+dw*dw) * (1.f / EMBED);
    float rs = rsqrtf(var + EPS_LN);
    float4 wv = *(const float4*)(n2w + t4);
    float4 bv = *(const float4*)(n2b + t4);
    float4 hv;
    hv.x = dx * rs * wv.x + bv.x + xv.x;
    hv.y = dy * rs * wv.y + bv.y + xv.y;
    hv.z = dz * rs * wv.z + bv.z + xv.z;
    hv.w = dw * rs * wv.w + bv.w + xv.w;
    *(float4*)(h + base + t4) = hv;

    s = hv.x + hv.y + hv.z + hv.w;
    float mu2 = block_sum128(s) * (1.f / EMBED);
    dx = hv.x-mu2; dy = hv.y-mu2; dz = hv.z-mu2; dw = hv.w-mu2;
    float var2 = block_sum128(dx*dx+dy*dy+dz*dz+dw*dw) * (1.f / EMBED);
    float rs2 = rsqrtf(var2 + EPS_LN);
    float4 w2 = *(const float4*)(m1w + t4);
    float4 b2 = *(const float4*)(m1b + t4);
    float4 zv;
    zv.x = dx * rs2 * w2.x + b2.x;
    zv.y = dy * rs2 * w2.y + b2.y;
    zv.z = dz * rs2 * w2.z + b2.z;
    zv.w = dw * rs2 * w2.w + b2.w;
    *(float4*)(z + base + t4) = zv;
}

// ---------------- GEMM: C[M,N] = A[M,K] @ W[N,K]^T (+epilogue) ----------------
// EPI: 0 = plain, 1 = +bias then exact GELU, 2 = +bias +residual
// 128x128 tile, BK=8, 256 threads, 8x8 microtile.
template<int EPI>
__global__ __launch_bounds__(256) void gemm_kernel(
    const float* __restrict__ A, const float* __restrict__ W,
    const float* __restrict__ bias, const float* __restrict__ res,
    float* __restrict__ C, int M, int N, int K)
{
    __shared__ float As[8 * 132];
    __shared__ float Bs[8 * 132];
    const int tid = threadIdx.x;
    const int tx = tid & 15, ty = tid >> 4;
    const int row0 = blockIdx.y * 128, col0 = blockIdx.x * 128;

    float acc[8][8];
    #pragma unroll
    for (int i = 0; i < 8; i++)
        #pragma unroll
        for (int j = 0; j < 8; j++) acc[i][j] = 0.f;

    const int lr = tid >> 1;
    const int ls = (tid & 1) * 4;
    const float* Ap = A + (size_t)(row0 + lr) * K + ls;
    const float* Wp = W + (size_t)(col0 + lr) * K + ls;

    for (int k0 = 0; k0 < K; k0 += 8) {
        float4 av = *(const float4*)(Ap + k0);
        float4 wv = *(const float4*)(Wp + k0);
        __syncthreads();
        As[(ls+0)*132 + lr] = av.x; As[(ls+1)*132 + lr] = av.y;
        As[(ls+2)*132 + lr] = av.z; As[(ls+3)*132 + lr] = av.w;
        Bs[(ls+0)*132 + lr] = wv.x; Bs[(ls+1)*132 + lr] = wv.y;
        Bs[(ls+2)*132 + lr] = wv.z; Bs[(ls+3)*132 + lr] = wv.w;
        __syncthreads();
        #pragma unroll
        for (int kk = 0; kk < 8; kk++) {
            float a[8], b[8];
            #pragma unroll
            for (int i = 0; i < 8; i++) a[i] = As[kk*132 + ty*8 + i];
            #pragma unroll
            for (int j = 0; j < 8; j++) b[j] = Bs[kk*132 + tx*8 + j];
            #pragma unroll
            for (int i = 0; i < 8; i++)
                #pragma unroll
                for (int j = 0; j < 8; j++)
                    acc[i][j] += a[i] * b[j];
        }
    }

    #pragma unroll
    for (int i = 0; i < 8; i++) {
        const int row = row0 + ty*8 + i;
        #pragma unroll
        for (int j = 0; j < 8; j++) {
            const int col = col0 + tx*8 + j;
            float v = acc[i][j];
            if (EPI == 1) {
                v += bias[col];
                v = 0.5f * v * (1.f + erff(v * 0.70710678118654752f));
            } else if (EPI == 2) {
                v += bias[col] + res[(size_t)row * N + col];
            }
            C[(size_t)row * N + col] = v;
        }
    }
}

// ---------------- differential flash attention ----------------
// grid (N/32, HEADS, BATCH), 256 threads. Each block: 32 q-rows of one v-head;
// processes sub-heads (2h, 2h+1) together; fuses lambda-combine + RMSNorm + 0.8.
__global__ __launch_bounds__(256) void attn_kernel(
    const float* __restrict__ q, const float* __restrict__ k, const float* __restrict__ v,
    const float* __restrict__ lq1, const float* __restrict__ lk1,
    const float* __restrict__ lq2, const float* __restrict__ lk2,
    const float* __restrict__ subw, float* __restrict__ out)
{
    constexpr int P = 36;  // padded row stride (floats) for 32-wide tiles
    __shared__ float sQ0[32*P], sQ1[32*P], sK0[32*P], sK1[32*P], sS0[32*P], sS1[32*P];
    __shared__ float sV[32*64];
    __shared__ float s_lam;

    const int tid = threadIdx.x;
    const int qt = blockIdx.x, h = blockIdx.y, b = blockIdx.z;

    if (tid == 0) {
        float s1 = 0.f, s2 = 0.f;
        #pragma unroll
        for (int i = 0; i < HD; i++) { s1 += lq1[i]*lk1[i]; s2 += lq2[i]*lk2[i]; }
        s_lam = expf(s1) - expf(s2) + LAMBDA_INIT;
    }

    const float scale = 0.17677669529663687f;  // 32^-0.5
    {
        const int rr = tid >> 3, c4 = (tid & 7) * 4;
        const float* qrow = q + ((size_t)(b*SEQ + qt*32 + rr)) * EMBED;
        float4 q0 = *(const float4*)(qrow + (2*h)*HD + c4);
        float4 q1 = *(const float4*)(qrow + (2*h+1)*HD + c4);
        sQ0[rr*P+c4+0]=q0.x*scale; sQ0[rr*P+c4+1]=q0.y*scale;
        sQ0[rr*P+c4+2]=q0.z*scale; sQ0[rr*P+c4+3]=q0.w*scale;
        sQ1[rr*P+c4+0]=q1.x*scale; sQ1[rr*P+c4+1]=q1.y*scale;
        sQ1[rr*P+c4+2]=q1.z*scale; sQ1[rr*P+c4+3]=q1.w*scale;
    }
    __syncthreads();
    const float lam = s_lam;

    const int r = tid >> 3, g = tid & 7;
    float m0 = -1e30f, m1 = -1e30f, l0 = 0.f, l1 = 0.f;
    float acc0[8], acc1[8];
    #pragma unroll
    for (int i = 0; i < 8; i++) { acc0[i] = 0.f; acc1[i] = 0.f; }

    for (int kt = 0; kt < SEQ/32; kt++) {
        // load K (both sub-heads) + V tile
        {
            const int rr = tid >> 3, c4 = (tid & 7) * 4;
            const float* krow = k + ((size_t)(b*SEQ + kt*32 + rr)) * EMBED;
            float4 k0 = *(const float4*)(krow + (2*h)*HD + c4);
            float4 k1 = *(const float4*)(krow + (2*h+1)*HD + c4);
            sK0[rr*P+c4+0]=k0.x; sK0[rr*P+c4+1]=k0.y; sK0[rr*P+c4+2]=k0.z; sK0[rr*P+c4+3]=k0.w;
            sK1[rr*P+c4+0]=k1.x; sK1[rr*P+c4+1]=k1.y; sK1[rr*P+c4+2]=k1.z; sK1[rr*P+c4+3]=k1.w;
            const float* vb = v + ((size_t)(b*SEQ + kt*32)) * EMBED + h*VD;
            #pragma unroll
            for (int e = 0; e < 2; e++) {
                int idx = tid + e*256;            // 0..511 float4s
                int vr = idx >> 4, vc4 = (idx & 15) * 4;
                *(float4*)(sV + vr*VD + vc4) = *(const float4*)(vb + (size_t)vr*EMBED + vc4);
            }
        }
        __syncthreads();

        // scores: S[r][c] for c = g*4..g*4+3, both sub-heads
        #pragma unroll
        for (int cc = 0; cc < 4; cc++) {
            const int c = g*4 + cc;
            float s0 = 0.f, s1 = 0.f;
            #pragma unroll
            for (int kk = 0; kk < 32; kk++) {
                s0 += sQ0[r*P+kk] * sK0[c*P+kk];
                s1 += sQ1[r*P+kk] * sK1[c*P+kk];
            }
            sS0[r*P+c] = s0; sS1[r*P+c] = s1;
        }
        __syncwarp();

        // online softmax (8 threads per row)
        float tm0 = -1e30f, tm1 = -1e30f;
        #pragma unroll
        for (int cc = 0; cc < 4; cc++) {
            tm0 = fmaxf(tm0, sS0[r*P+g*4+cc]);
            tm1 = fmaxf(tm1, sS1[r*P+g*4+cc]);
        }
        #pragma unroll
        for (int o = 1; o < 8; o <<= 1) {
            tm0 = fmaxf(tm0, __shfl_xor_sync(0xffffffffu, tm0, o));
            tm1 = fmaxf(tm1, __shfl_xor_sync(0xffffffffu, tm1, o));
        }
        const float nm0 = fmaxf(m0, tm0), nm1 = fmaxf(m1, tm1);
        const float f0 = expf(m0 - nm0), f1 = expf(m1 - nm1);
        float ps0 = 0.f, ps1 = 0.f;
        #pragma unroll
        for (int cc = 0; cc < 4; cc++) {
            float p0 = expf(sS0[r*P+g*4+cc] - nm0);
            float p1 = expf(sS1[r*P+g*4+cc] - nm1);
            sS0[r*P+g*4+cc] = p0; sS1[r*P+g*4+cc] = p1;
            ps0 += p0; ps1 += p1;
        }
        __syncwarp();
        #pragma unroll
        for (int o = 1; o < 8; o <<= 1) {
            ps0 += __shfl_xor_sync(0xffffffffu, ps0, o);
            ps1 += __shfl_xor_sync(0xffffffffu, ps1, o);
        }
        l0 = l0 * f0 + ps0; l1 = l1 * f1 + ps1;
        m0 = nm0; m1 = nm1;

        #pragma unroll
        for (int i = 0; i < 8; i++) { acc0[i] *= f0; acc1[i] *= f1; }
        #pragma unroll 4
        for (int j = 0; j < 32; j++) {
            const float p0 = sS0[r*P+j], p1 = sS1[r*P+j];
            #pragma unroll
            for (int i = 0; i < 8; i++) {
                const float vv = sV[j*VD + g*8 + i];
                acc0[i] += p0 * vv;
                acc1[i] += p1 * vv;
            }
        }
        __syncthreads();
    }

    // epilogue: diff combine, RMSNorm over 64 dims, * (1 - lambda_init)
    const float inv0 = 1.f / l0, inv1 = 1.f / l1;
    float o[8]; float ss = 0.f;
    #pragma unroll
    for (int i = 0; i < 8; i++) {
        o[i] = acc0[i] * inv0 - lam * acc1[i] * inv1;
        ss += o[i] * o[i];
    }
    #pragma unroll
    for (int oo = 1; oo < 8; oo <<= 1)
        ss += __shfl_xor_sync(0xffffffffu, ss, oo);
    const float rsn = rsqrtf(ss * (1.f / VD) + EPS_LN);
    float* orow = out + ((size_t)(b*SEQ + qt*32 + r)) * EMBED + h*VD + g*8;
    #pragma unroll
    for (int i = 0; i < 8; i++)
        orow[i] = o[i] * rsn * subw[g*8 + i] * (1.f - LAMBDA_INIT);
}

// ---------------- host launch ----------------
extern "C" void kernel_launch(void* const* d_in, const int* in_sizes, int n_in,
                              void* d_out, int out_size)
{
    (void)in_sizes; (void)n_in; (void)out_size;
    const float* x     = (const float*)d_in[0];
    const float* Wq    = (const float*)d_in[1];
    const float* Wk    = (const float*)d_in[2];
    const float* Wv    = (const float*)d_in[3];
    const float* Wo    = (const float*)d_in[4];
    const float* lq1   = (const float*)d_in[5];
    const float* lk1   = (const float*)d_in[6];
    const float* lq2   = (const float*)d_in[7];
    const float* lk2   = (const float*)d_in[8];
    const float* subw  = (const float*)d_in[9];
    const float* n1w   = (const float*)d_in[10];
    const float* n1b   = (const float*)d_in[11];
    const float* n2w   = (const float*)d_in[12];
    const float* n2b   = (const float*)d_in[13];
    const float* mln1w = (const float*)d_in[14];
    const float* mln1b = (const float*)d_in[15];
    const float* mW1   = (const float*)d_in[16];
    const float* mb1   = (const float*)d_in[17];
    const float* mln2w = (const float*)d_in[18];
    const float* mln2b = (const float*)d_in[19];
    const float* mW2   = (const float*)d_in[20];
    const float* mb2   = (const float*)d_in[21];
    float* out = (float*)d_out;

    float *xn, *qb, *kb, *vb, *ao, *ab, *hb, *z1, *z2;
    cudaGetSymbolAddress((void**)&xn, g_xn);
    cudaGetSymbolAddress((void**)&qb, g_q);
    cudaGetSymbolAddress((void**)&kb, g_k);
    cudaGetSymbolAddress((void**)&vb, g_v);
    cudaGetSymbolAddress((void**)&ao, g_ao);
    cudaGetSymbolAddress((void**)&ab, g_a);
    cudaGetSymbolAddress((void**)&hb, g_h);
    cudaGetSymbolAddress((void**)&z1, g_z1);
    cudaGetSymbolAddress((void**)&z2, g_z2);

    const dim3 g512(EMBED/128, BN/128);   // (4, 64)
    const dim3 g2048(EXPD/128, BN/128);   // (16, 64)

    // 1. xn = LN(x)
    ln_kernel<EMBED><<<BN, 128>>>(x, n1w, n1b, xn);
    // 2. q/k/v = xn @ W^T
    gemm_kernel<0><<<g512, 256>>>(xn, Wq, nullptr, nullptr, qb, BN, EMBED, EMBED);
    gemm_kernel<0><<<g512, 256>>>(xn, Wk, nullptr, nullptr, kb, BN, EMBED, EMBED);
    gemm_kernel<0><<<g512, 256>>>(xn, Wv, nullptr, nullptr, vb, BN, EMBED, EMBED);
    // 3. differential attention (fused combine + rmsnorm)
    attn_kernel<<<dim3(SEQ/32, HEADS, BATCH), 256>>>(qb, kb, vb, lq1, lk1, lq2, lk2, subw, ao);
    // 4. a = ao @ Wo^T
    gemm_kernel<0><<<g512, 256>>>(ao, Wo, nullptr, nullptr, ab, BN, EMBED, EMBED);
    // 5. h = LN(a)+x ; z = LN(h)   (z reuses xn buffer)
    hz_kernel<<<BN, 128>>>(ab, x, n2w, n2b, mln1w, mln1b, hb, xn);
    // 6. z1 = GELU(z @ mW1^T + mb1)
    gemm_kernel<1><<<g2048, 256>>>(xn, mW1, mb1, nullptr, z1, BN, EXPD, EMBED);
    // 7. z2 = LN(z1)
    ln_kernel<EXPD><<<BN, 128>>>(z1, mln2w, mln2b, z2);
    // 8. out = z2 @ mW2^T + mb2 + h
    gemm_kernel<2><<<g512, 256>>>(z2, mW2, mb2, hb, out, BN, EMBED, EXPD);
}

// round 6
// speedup vs baseline: 4.9426x; 4.9426x over previous
#include <cuda_runtime.h>
#include <cuda_bf16.h>
#include <math.h>
#include <stdint.h>

// ---------------- problem constants ----------------
#define BATCH 8
#define SEQ   1024
#define EMBED 512
#define BN    (BATCH*SEQ)          // 8192
#define HEADS 8
#define HD    32                   // diff-attn sub-head dim
#define VD    64                   // v head dim = 2*HD
#define EXPD  2048                 // 4*EMBED
#define LAMBDA_INIT 0.2f
#define EPS_LN 1e-5f

// ---------------- device scratch (static, no allocation) ----------------
__device__ float g_xn[(size_t)BN*EMBED];
__device__ float g_q [(size_t)BN*EMBED];
__device__ float g_k [(size_t)BN*EMBED];
__device__ float g_v [(size_t)BN*EMBED];
__device__ float g_ao[(size_t)BN*EMBED];
__device__ float g_a [(size_t)BN*EMBED];
__device__ float g_h [(size_t)BN*EMBED];
__device__ float g_z1[(size_t)BN*EXPD];
__device__ float g_z2[(size_t)BN*EXPD];

// ---------------- block reduction (128 threads) ----------------
__device__ __forceinline__ float block_sum128(float v) {
    __shared__ float sm[4];
    #pragma unroll
    for (int o = 16; o; o >>= 1) v += __shfl_xor_sync(0xffffffffu, v, o);
    if ((threadIdx.x & 31) == 0) sm[threadIdx.x >> 5] = v;
    __syncthreads();
    float t = sm[0] + sm[1] + sm[2] + sm[3];
    __syncthreads();
    return t;
}

// ---------------- generic LayerNorm ----------------
template<int D>
__global__ __launch_bounds__(128) void ln_kernel(
    const float* __restrict__ in, const float* __restrict__ w,
    const float* __restrict__ b, float* __restrict__ out)
{
    constexpr int V = D / 512;
    const size_t base = (size_t)blockIdx.x * D;
    float4 xv[V];
    float s = 0.f;
    #pragma unroll
    for (int j = 0; j < V; j++) {
        xv[j] = *(const float4*)(in + base + (size_t)(j * 128 + threadIdx.x) * 4);
        s += xv[j].x + xv[j].y + xv[j].z + xv[j].w;
    }
    const float mu = block_sum128(s) * (1.f / D);
    float vs = 0.f;
    #pragma unroll
    for (int j = 0; j < V; j++) {
        float dx = xv[j].x - mu, dy = xv[j].y - mu, dz = xv[j].z - mu, dw = xv[j].w - mu;
        vs += dx*dx + dy*dy + dz*dz + dw*dw;
    }
    const float var = block_sum128(vs) * (1.f / D);
    const float rs = rsqrtf(var + EPS_LN);
    #pragma unroll
    for (int j = 0; j < V; j++) {
        int idx = (j * 128 + threadIdx.x) * 4;
        float4 wv = *(const float4*)(w + idx);
        float4 bv = *(const float4*)(b + idx);
        float4 o;
        o.x = (xv[j].x - mu) * rs * wv.x + bv.x;
        o.y = (xv[j].y - mu) * rs * wv.y + bv.y;
        o.z = (xv[j].z - mu) * rs * wv.z + bv.z;
        o.w = (xv[j].w - mu) * rs * wv.w + bv.w;
        *(float4*)(out + base + idx) = o;
    }
}

// ---------------- fused: h = LN(a)+x ; z = LN(h) ----------------
__global__ __launch_bounds__(128) void hz_kernel(
    const float* __restrict__ a, const float* __restrict__ x,
    const float* __restrict__ n2w, const float* __restrict__ n2b,
    const float* __restrict__ m1w, const float* __restrict__ m1b,
    float* __restrict__ h, float* __restrict__ z)
{
    const size_t base = (size_t)blockIdx.x * EMBED;
    const int t4 = threadIdx.x * 4;
    float4 av = *(const float4*)(a + base + t4);
    float4 xv = *(const float4*)(x + base + t4);

    float s = av.x + av.y + av.z + av.w;
    float mu = block_sum128(s) * (1.f / EMBED);
    float dx = av.x-mu, dy = av.y-mu, dz = av.z-mu, dw = av.w-mu;
    float var = block_sum128(dx*dx+dy*dy+dz*dz+dw*dw) * (1.f / EMBED);
    float rs = rsqrtf(var + EPS_LN);
    float4 wv = *(const float4*)(n2w + t4);
    float4 bv = *(const float4*)(n2b + t4);
    float4 hv;
    hv.x = dx * rs * wv.x + bv.x + xv.x;
    hv.y = dy * rs * wv.y + bv.y + xv.y;
    hv.z = dz * rs * wv.z + bv.z + xv.z;
    hv.w = dw * rs * wv.w + bv.w + xv.w;
    *(float4*)(h + base + t4) = hv;

    s = hv.x + hv.y + hv.z + hv.w;
    float mu2 = block_sum128(s) * (1.f / EMBED);
    dx = hv.x-mu2; dy = hv.y-mu2; dz = hv.z-mu2; dw = hv.w-mu2;
    float var2 = block_sum128(dx*dx+dy*dy+dz*dz+dw*dw) * (1.f / EMBED);
    float rs2 = rsqrtf(var2 + EPS_LN);
    float4 w2 = *(const float4*)(m1w + t4);
    float4 b2 = *(const float4*)(m1b + t4);
    float4 zv;
    zv.x = dx * rs2 * w2.x + b2.x;
    zv.y = dy * rs2 * w2.y + b2.y;
    zv.z = dz * rs2 * w2.z + b2.z;
    zv.w = dw * rs2 * w2.w + b2.w;
    *(float4*)(z + base + t4) = zv;
}

// ---------------- bf16x3 tensor-core GEMM ----------------
// C[M,N] = A[M,K] @ W[N,K]^T  via mma.sync m16n8k16 bf16, error-compensated:
// D = Ah*Bh + Ah*Bl + Al*Bh (fp32 acc).  EPI: 0 plain, 1 bias+GELU, 2 bias+res.
// 128x128 tile, BK=32, 256 threads (8 warps as 2x4 -> warp tile 64x32).

__device__ __forceinline__ void mma16816(float d[4],
    uint32_t a0, uint32_t a1, uint32_t a2, uint32_t a3,
    uint32_t b0, uint32_t b1)
{
    asm volatile(
        "mma.sync.aligned.m16n8k16.row.col.f32.bf16.bf16.f32 "
        "{%0,%1,%2,%3}, {%4,%5,%6,%7}, {%8,%9}, {%0,%1,%2,%3};\n"
        : "+f"(d[0]), "+f"(d[1]), "+f"(d[2]), "+f"(d[3])
        : "r"(a0), "r"(a1), "r"(a2), "r"(a3), "r"(b0), "r"(b1));
}

__device__ __forceinline__ void split2(float x, float y, uint32_t& hi, uint32_t& lo) {
    __nv_bfloat16 hx = __float2bfloat16_rn(x);
    __nv_bfloat16 hy = __float2bfloat16_rn(y);
    __nv_bfloat16 lx = __float2bfloat16_rn(x - __bfloat162float(hx));
    __nv_bfloat16 ly = __float2bfloat16_rn(y - __bfloat162float(hy));
    __nv_bfloat162 h2 = __halves2bfloat162(hx, hy);
    __nv_bfloat162 l2 = __halves2bfloat162(lx, ly);
    hi = *(uint32_t*)&h2;
    lo = *(uint32_t*)&l2;
}

template<int EPI>
__global__ __launch_bounds__(256) void mma_gemm(
    const float* __restrict__ A, const float* __restrict__ W,
    const float* __restrict__ bias, const float* __restrict__ res,
    float* __restrict__ C, int M, int N, int K)
{
    // smem word stride 20 (=40 halves) -> conflict-free fragment loads
    __shared__ uint32_t AsH[128*20], AsL[128*20], BsH[128*20], BsL[128*20];

    const int tid = threadIdx.x;
    const int lane = tid & 31, warp = tid >> 5;
    const int wm = warp >> 2, wn = warp & 3;          // 2 x 4 warps
    const int lq = lane >> 2, lr = lane & 3;
    const int row0 = blockIdx.y * 128, col0 = blockIdx.x * 128;

    float acc[4][4][4];
    #pragma unroll
    for (int i = 0; i < 4; i++)
        #pragma unroll
        for (int j = 0; j < 4; j++)
            #pragma unroll
            for (int t = 0; t < 4; t++) acc[i][j][t] = 0.f;

    for (int k0 = 0; k0 < K; k0 += 32) {
        __syncthreads();
        // load + split 128x32 of A and W
        #pragma unroll
        for (int e = 0; e < 4; e++) {
            int lin = tid + e * 256;          // 0..1023
            int r = lin >> 3;                 // 0..127
            int c4 = (lin & 7) << 2;          // 0,4,..28
            float4 va = *(const float4*)(A + (size_t)(row0 + r) * K + k0 + c4);
            uint32_t h0, l0, h1, l1;
            split2(va.x, va.y, h0, l0);
            split2(va.z, va.w, h1, l1);
            int wadr = r * 20 + (c4 >> 1);
            AsH[wadr] = h0; AsH[wadr + 1] = h1;
            AsL[wadr] = l0; AsL[wadr + 1] = l1;
            float4 vw = *(const float4*)(W + (size_t)(col0 + r) * K + k0 + c4);
            split2(vw.x, vw.y, h0, l0);
            split2(vw.z, vw.w, h1, l1);
            BsH[wadr] = h0; BsH[wadr + 1] = h1;
            BsL[wadr] = l0; BsL[wadr + 1] = l1;
        }
        __syncthreads();

        #pragma unroll
        for (int ks = 0; ks < 2; ks++) {
            const int kw = ks * 8;
            uint32_t ah[4][4], al[4][4], bh[4][2], bl[4][2];
            #pragma unroll
            for (int mf = 0; mf < 4; mf++) {
                int aw = (wm * 64 + mf * 16 + lq) * 20 + kw + lr;
                ah[mf][0] = AsH[aw];       ah[mf][1] = AsH[aw + 160];
                ah[mf][2] = AsH[aw + 4];   ah[mf][3] = AsH[aw + 164];
                al[mf][0] = AsL[aw];       al[mf][1] = AsL[aw + 160];
                al[mf][2] = AsL[aw + 4];   al[mf][3] = AsL[aw + 164];
            }
            #pragma unroll
            for (int nf = 0; nf < 4; nf++) {
                int bw = (wn * 32 + nf * 8 + lq) * 20 + kw + lr;
                bh[nf][0] = BsH[bw];  bh[nf][1] = BsH[bw + 4];
                bl[nf][0] = BsL[bw];  bl[nf][1] = BsL[bw + 4];
            }
            #pragma unroll
            for (int mf = 0; mf < 4; mf++)
                #pragma unroll
                for (int nf = 0; nf < 4; nf++) {
                    mma16816(acc[mf][nf], ah[mf][0], ah[mf][1], ah[mf][2], ah[mf][3],
                             bh[nf][0], bh[nf][1]);
                    mma16816(acc[mf][nf], ah[mf][0], ah[mf][1], ah[mf][2], ah[mf][3],
                             bl[nf][0], bl[nf][1]);
                    mma16816(acc[mf][nf], al[mf][0], al[mf][1], al[mf][2], al[mf][3],
                             bh[nf][0], bh[nf][1]);
                }
        }
    }

    // epilogue
    #pragma unroll
    for (int mf = 0; mf < 4; mf++) {
        #pragma unroll
        for (int nf = 0; nf < 4; nf++) {
            int row = row0 + wm * 64 + mf * 16 + lq;
            int col = col0 + wn * 32 + nf * 8 + lr * 2;
            #pragma unroll
            for (int half = 0; half < 2; half++) {
                int rr = row + half * 8;
                float v0 = acc[mf][nf][half * 2 + 0];
                float v1 = acc[mf][nf][half * 2 + 1];
                if (EPI == 1) {
                    v0 += bias[col];     v1 += bias[col + 1];
                    v0 = 0.5f * v0 * (1.f + erff(v0 * 0.70710678118654752f));
                    v1 = 0.5f * v1 * (1.f + erff(v1 * 0.70710678118654752f));
                } else if (EPI == 2) {
                    v0 += bias[col]     + res[(size_t)rr * N + col];
                    v1 += bias[col + 1] + res[(size_t)rr * N + col + 1];
                }
                *(float2*)(C + (size_t)rr * N + col) = make_float2(v0, v1);
            }
        }
    }
}

// ---------------- differential flash attention (register-tiled) ----------------
// grid (SEQ/64, HEADS, BATCH), 256 threads. 64 q-rows/block, 64-key tiles.
// Scores computed base-2 (log2e folded into scale) -> exp2f.
extern __shared__ float sm_attn[];

#define PS 68   // smem row stride (floats)

__global__ __launch_bounds__(256) void attn_kernel(
    const float* __restrict__ q, const float* __restrict__ k, const float* __restrict__ v,
    const float* __restrict__ lq1, const float* __restrict__ lk1,
    const float* __restrict__ lq2, const float* __restrict__ lk2,
    const float* __restrict__ subw, float* __restrict__ out)
{
    float* sQ0 = sm_attn;            // [32][PS] (k-major, transposed)
    float* sQ1 = sQ0 + 32*PS;
    float* sK0 = sQ1 + 32*PS;
    float* sK1 = sK0 + 32*PS;
    float* sS0 = sK1 + 32*PS;        // [64][PS]
    float* sS1 = sS0 + 64*PS;
    float* sV  = sS1 + 64*PS;        // [64][PS]
    float* sF0 = sV  + 64*PS;        // [64] rescale factors
    float* sF1 = sF0 + 64;
    float* sL0 = sF1 + 64;           // [64] running denominators
    float* sL1 = sL0 + 64;
    __shared__ float s_lam;

    const int tid = threadIdx.x;
    const int qt = blockIdx.x, h = blockIdx.y, b = blockIdx.z;

    if (tid == 0) {
        float s1 = 0.f, s2 = 0.f;
        #pragma unroll
        for (int i = 0; i < HD; i++) { s1 += lq1[i]*lk1[i]; s2 += lq2[i]*lk2[i]; }
        s_lam = expf(s1) - expf(s2) + LAMBDA_INIT;
    }

    // scale = log2(e) / sqrt(32)
    const float scale = 0.17677669529663687f * 1.4426950408889634f;

    // load Q (both sub-heads), transposed + scaled
    #pragma unroll
    for (int e = 0; e < 4; e++) {
        int lin = tid + e * 256;             // 0..1023
        int head = lin >> 9;
        int rem = lin & 511;
        int row = rem >> 3;                  // 0..63
        int c4 = (rem & 7) << 2;             // 0..28
        float4 qv = *(const float4*)(q + ((size_t)(b*SEQ + qt*64 + row))*EMBED + (2*h + head)*HD + c4);
        float* dst = head ? sQ1 : sQ0;
        dst[(c4+0)*PS + row] = qv.x*scale;
        dst[(c4+1)*PS + row] = qv.y*scale;
        dst[(c4+2)*PS + row] = qv.z*scale;
        dst[(c4+3)*PS + row] = qv.w*scale;
    }

    const int ty = tid >> 4, tx = tid & 15;      // 16x16 micro-tile grid
    const int sr = tid >> 2, spart = tid & 3;    // softmax: 4 threads/row

    float m0 = -1e30f, m1 = -1e30f, l0 = 0.f, l1 = 0.f;
    float acc0[4][4], acc1[4][4];
    #pragma unroll
    for (int i = 0; i < 4; i++)
        #pragma unroll
        for (int j = 0; j < 4; j++) { acc0[i][j] = 0.f; acc1[i][j] = 0.f; }

    for (int kt = 0; kt < SEQ/64; kt++) {
        __syncthreads();
        // ---- load K (transposed) + V ----
        #pragma unroll
        for (int e = 0; e < 4; e++) {
            int lin = tid + e * 256;
            int head = lin >> 9;
            int rem = lin & 511;
            int row = rem >> 3;
            int c4 = (rem & 7) << 2;
            float4 kv = *(const float4*)(k + ((size_t)(b*SEQ + kt*64 + row))*EMBED + (2*h + head)*HD + c4);
            float* dst = head ? sK1 : sK0;
            dst[(c4+0)*PS + row] = kv.x;
            dst[(c4+1)*PS + row] = kv.y;
            dst[(c4+2)*PS + row] = kv.z;
            dst[(c4+3)*PS + row] = kv.w;
        }
        #pragma unroll
        for (int e = 0; e < 4; e++) {
            int lin = tid + e * 256;
            int row = lin >> 4;                  // 0..63
            int c4 = (lin & 15) << 2;            // 0..60
            float4 vv = *(const float4*)(v + ((size_t)(b*SEQ + kt*64 + row))*EMBED + h*VD + c4);
            *(float4*)(sV + row*PS + c4) = vv;
        }
        __syncthreads();

        // ---- scores: 4x4 micro-tile per thread, both sub-heads ----
        {
            float s0a[4][4], s1a[4][4];
            #pragma unroll
            for (int i = 0; i < 4; i++)
                #pragma unroll
                for (int j = 0; j < 4; j++) { s0a[i][j] = 0.f; s1a[i][j] = 0.f; }
            #pragma unroll 8
            for (int kk = 0; kk < 32; kk++) {
                float4 a0 = *(const float4*)(sQ0 + kk*PS + ty*4);
                float4 a1 = *(const float4*)(sQ1 + kk*PS + ty*4);
                float4 b0 = *(const float4*)(sK0 + kk*PS + tx*4);
                float4 b1 = *(const float4*)(sK1 + kk*PS + tx*4);
                float aa0[4] = {a0.x,a0.y,a0.z,a0.w};
                float aa1[4] = {a1.x,a1.y,a1.z,a1.w};
                float bb0[4] = {b0.x,b0.y,b0.z,b0.w};
                float bb1[4] = {b1.x,b1.y,b1.z,b1.w};
                #pragma unroll
                for (int i = 0; i < 4; i++)
                    #pragma unroll
                    for (int j = 0; j < 4; j++) {
                        s0a[i][j] += aa0[i]*bb0[j];
                        s1a[i][j] += aa1[i]*bb1[j];
                    }
            }
            #pragma unroll
            for (int i = 0; i < 4; i++)
                #pragma unroll
                for (int j = 0; j < 4; j++) {
                    sS0[(ty*4+i)*PS + tx*4+j] = s0a[i][j];
                    sS1[(ty*4+i)*PS + tx*4+j] = s1a[i][j];
                }
        }
        __syncthreads();

        // ---- online softmax (base 2), 4 threads per row x 16 cols ----
        {
            float v0[16], v1[16];
            float tm0 = -1e30f, tm1 = -1e30f;
            #pragma unroll
            for (int c4 = 0; c4 < 4; c4++) {
                float4 f0 = *(const float4*)(sS0 + sr*PS + spart*16 + c4*4);
                float4 f1 = *(const float4*)(sS1 + sr*PS + spart*16 + c4*4);
                v0[c4*4+0]=f0.x; v0[c4*4+1]=f0.y; v0[c4*4+2]=f0.z; v0[c4*4+3]=f0.w;
                v1[c4*4+0]=f1.x; v1[c4*4+1]=f1.y; v1[c4*4+2]=f1.z; v1[c4*4+3]=f1.w;
                tm0 = fmaxf(tm0, fmaxf(fmaxf(f0.x,f0.y), fmaxf(f0.z,f0.w)));
                tm1 = fmaxf(tm1, fmaxf(fmaxf(f1.x,f1.y), fmaxf(f1.z,f1.w)));
            }
            #pragma unroll
            for (int o = 1; o < 4; o <<= 1) {
                tm0 = fmaxf(tm0, __shfl_xor_sync(0xffffffffu, tm0, o));
                tm1 = fmaxf(tm1, __shfl_xor_sync(0xffffffffu, tm1, o));
            }
            const float nm0 = fmaxf(m0, tm0), nm1 = fmaxf(m1, tm1);
            const float f0 = exp2f(m0 - nm0), f1 = exp2f(m1 - nm1);
            float ps0 = 0.f, ps1 = 0.f;
            #pragma unroll
            for (int c = 0; c < 16; c++) {
                v0[c] = exp2f(v0[c] - nm0);
                v1[c] = exp2f(v1[c] - nm1);
                ps0 += v0[c]; ps1 += v1[c];
            }
            #pragma unroll
            for (int c4 = 0; c4 < 4; c4++) {
                *(float4*)(sS0 + sr*PS + spart*16 + c4*4) =
                    make_float4(v0[c4*4+0], v0[c4*4+1], v0[c4*4+2], v0[c4*4+3]);
                *(float4*)(sS1 + sr*PS + spart*16 + c4*4) =
                    make_float4(v1[c4*4+0], v1[c4*4+1], v1[c4*4+2], v1[c4*4+3]);
            }
            #pragma unroll
            for (int o = 1; o < 4; o <<= 1) {
                ps0 += __shfl_xor_sync(0xffffffffu, ps0, o);
                ps1 += __shfl_xor_sync(0xffffffffu, ps1, o);
            }
            l0 = l0 * f0 + ps0; l1 = l1 * f1 + ps1;
            m0 = nm0; m1 = nm1;
            if (spart == 0) {
                sF0[sr] = f0; sF1[sr] = f1;
                sL0[sr] = l0; sL1[sr] = l1;
            }
        }
        __syncthreads();

        // ---- PV accumulate: rows ty*4+i, v-cols tx*4+j ----
        {
            float f0r[4], f1r[4];
            #pragma unroll
            for (int i = 0; i < 4; i++) { f0r[i] = sF0[ty*4+i]; f1r[i] = sF1[ty*4+i]; }
            #pragma unroll
            for (int i = 0; i < 4; i++)
                #pragma unroll
                for (int j = 0; j < 4; j++) { acc0[i][j] *= f0r[i]; acc1[i][j] *= f1r[i]; }
            #pragma unroll 8
            for (int jk = 0; jk < 64; jk++) {
                float4 vv = *(const float4*)(sV + jk*PS + tx*4);
                float vva[4] = {vv.x, vv.y, vv.z, vv.w};
                float p0[4], p1[4];
                #pragma unroll
                for (int i = 0; i < 4; i++) {
                    p0[i] = sS0[(ty*4+i)*PS + jk];
                    p1[i] = sS1[(ty*4+i)*PS + jk];
                }
                #pragma unroll
                for (int i = 0; i < 4; i++)
                    #pragma unroll
                    for (int j = 0; j < 4; j++) {
                        acc0[i][j] += p0[i]*vva[j];
                        acc1[i][j] += p1[i]*vva[j];
                    }
            }
        }
    }

    // ---- epilogue: combine, rmsnorm(64), write ----
    const float lam = s_lam;
    float linv0[4], linv1[4];
    #pragma unroll
    for (int i = 0; i < 4; i++) {
        linv0[i] = 1.f / sL0[ty*4+i];
        linv1[i] = 1.f / sL1[ty*4+i];
    }
    float o[4][4], ss[4];
    #pragma unroll
    for (int i = 0; i < 4; i++) {
        ss[i] = 0.f;
        #pragma unroll
        for (int j = 0; j < 4; j++) {
            o[i][j] = acc0[i][j]*linv0[i] - lam*acc1[i][j]*linv1[i];
            ss[i] += o[i][j]*o[i][j];
        }
    }
    #pragma unroll
    for (int i = 0; i < 4; i++)
        #pragma unroll
        for (int off = 1; off < 16; off <<= 1)
            ss[i] += __shfl_xor_sync(0xffffffffu, ss[i], off);
    float4 wv = *(const float4*)(subw + tx*4);
    float wva[4] = {wv.x, wv.y, wv.z, wv.w};
    #pragma unroll
    for (int i = 0; i < 4; i++) {
        const float rsn = rsqrtf(ss[i] * (1.f / VD) + EPS_LN) * (1.f - LAMBDA_INIT);
        float4 ov;
        ov.x = o[i][0]*rsn*wva[0];
        ov.y = o[i][1]*rsn*wva[1];
        ov.z = o[i][2]*rsn*wva[2];
        ov.w = o[i][3]*rsn*wva[3];
        *(float4*)(out + ((size_t)(b*SEQ + qt*64 + ty*4 + i))*EMBED + h*VD + tx*4) = ov;
    }
}

#define ATTN_SMEM ((4*32*PS + 2*64*PS + 64*PS + 4*64) * (int)sizeof(float))

// ---------------- host launch ----------------
extern "C" void kernel_launch(void* const* d_in, const int* in_sizes, int n_in,
                              void* d_out, int out_size)
{
    (void)in_sizes; (void)n_in; (void)out_size;
    const float* x     = (const float*)d_in[0];
    const float* Wq    = (const float*)d_in[1];
    const float* Wk    = (const float*)d_in[2];
    const float* Wv    = (const float*)d_in[3];
    const float* Wo    = (const float*)d_in[4];
    const float* lq1   = (const float*)d_in[5];
    const float* lk1   = (const float*)d_in[6];
    const float* lq2   = (const float*)d_in[7];
    const float* lk2   = (const float*)d_in[8];
    const float* subw  = (const float*)d_in[9];
    const float* n1w   = (const float*)d_in[10];
    const float* n1b   = (const float*)d_in[11];
    const float* n2w   = (const float*)d_in[12];
    const float* n2b   = (const float*)d_in[13];
    const float* mln1w = (const float*)d_in[14];
    const float* mln1b = (const float*)d_in[15];
    const float* mW1   = (const float*)d_in[16];
    const float* mb1   = (const float*)d_in[17];
    const float* mln2w = (const float*)d_in[18];
    const float* mln2b = (const float*)d_in[19];
    const float* mW2   = (const float*)d_in[20];
    const float* mb2   = (const float*)d_in[21];
    float* out = (float*)d_out;

    float *xn, *qb, *kb, *vb, *ao, *ab, *hb, *z1, *z2;
    cudaGetSymbolAddress((void**)&xn, g_xn);
    cudaGetSymbolAddress((void**)&qb, g_q);
    cudaGetSymbolAddress((void**)&kb, g_k);
    cudaGetSymbolAddress((void**)&vb, g_v);
    cudaGetSymbolAddress((void**)&ao, g_ao);
    cudaGetSymbolAddress((void**)&ab, g_a);
    cudaGetSymbolAddress((void**)&hb, g_h);
    cudaGetSymbolAddress((void**)&z1, g_z1);
    cudaGetSymbolAddress((void**)&z2, g_z2);

    static bool attr_set = false;
    if (!attr_set) {
        cudaFuncSetAttribute(attn_kernel,
            cudaFuncAttributeMaxDynamicSharedMemorySize, ATTN_SMEM);
        attr_set = true;
    }

    const dim3 g512(EMBED/128, BN/128);   // (4, 64)
    const dim3 g2048(EXPD/128, BN/128);   // (16, 64)

    // 1. xn = LN(x)
    ln_kernel<EMBED><<<BN, 128>>>(x, n1w, n1b, xn);
    // 2. q/k/v = xn @ W^T  (bf16x3 tensor cores)
    mma_gemm<0><<<g512, 256>>>(xn, Wq, nullptr, nullptr, qb, BN, EMBED, EMBED);
    mma_gemm<0><<<g512, 256>>>(xn, Wk, nullptr, nullptr, kb, BN, EMBED, EMBED);
    mma_gemm<0><<<g512, 256>>>(xn, Wv, nullptr, nullptr, vb, BN, EMBED, EMBED);
    // 3. differential attention (fused combine + rmsnorm)
    attn_kernel<<<dim3(SEQ/64, HEADS, BATCH), 256, ATTN_SMEM>>>(
        qb, kb, vb, lq1, lk1, lq2, lk2, subw, ao);
    // 4. a = ao @ Wo^T
    mma_gemm<0><<<g512, 256>>>(ao, Wo, nullptr, nullptr, ab, BN, EMBED, EMBED);
    // 5. h = LN(a)+x ; z = LN(h)   (z reuses xn buffer)
    hz_kernel<<<BN, 128>>>(ab, x, n2w, n2b, mln1w, mln1b, hb, xn);
    // 6. z1 = GELU(z @ mW1^T + mb1)
    mma_gemm<1><<<g2048, 256>>>(xn, mW1, mb1, nullptr, z1, BN, EXPD, EMBED);
    // 7. z2 = LN(z1)
    ln_kernel<EXPD><<<BN, 128>>>(z1, mln2w, mln2b, z2);
    // 8. out = z2 @ mW2^T + mb2 + h
    mma_gemm<2><<<g512, 256>>>(z2, mW2, mb2, hb, out, BN, EMBED, EXPD);
}

// round 7
// speedup vs baseline: 5.7407x; 1.1615x over previous
#include <cuda_runtime.h>
#include <cuda_bf16.h>
#include <math.h>
#include <stdint.h>

// ---------------- problem constants ----------------
#define BATCH 8
#define SEQ   1024
#define EMBED 512
#define BN    (BATCH*SEQ)          // 8192
#define HEADS 8
#define HD    32
#define VD    64
#define EXPD  2048
#define LAMBDA_INIT 0.2f
#define EPS_LN 1e-5f

// ---------------- device scratch ----------------
__device__ float g_q [(size_t)BN*EMBED];
__device__ float g_k [(size_t)BN*EMBED];
__device__ float g_v [(size_t)BN*EMBED];
__device__ float g_ab[(size_t)BN*EMBED];
__device__ float g_h [(size_t)BN*EMBED];
__device__ float g_z1[(size_t)BN*EXPD];
// packed bf16x2 planes (hi/lo)
__device__ uint32_t g_xnh[(size_t)BN*EMBED/2], g_xnl[(size_t)BN*EMBED/2];
__device__ uint32_t g_aoh[(size_t)BN*EMBED/2], g_aol[(size_t)BN*EMBED/2];
__device__ uint32_t g_z2h[(size_t)BN*EXPD/2],  g_z2l[(size_t)BN*EXPD/2];
__device__ uint32_t g_wqh[EMBED*EMBED/2], g_wql[EMBED*EMBED/2];
__device__ uint32_t g_wkh[EMBED*EMBED/2], g_wkl[EMBED*EMBED/2];
__device__ uint32_t g_wvh[EMBED*EMBED/2], g_wvl[EMBED*EMBED/2];
__device__ uint32_t g_woh[EMBED*EMBED/2], g_wol[EMBED*EMBED/2];
__device__ uint32_t g_w1h[EXPD*EMBED/2],  g_w1l[EXPD*EMBED/2];
__device__ uint32_t g_w2h[EMBED*EXPD/2],  g_w2l[EMBED*EXPD/2];

__device__ __forceinline__ void split2(float x, float y, uint32_t& hi, uint32_t& lo) {
    __nv_bfloat16 hx = __float2bfloat16_rn(x);
    __nv_bfloat16 hy = __float2bfloat16_rn(y);
    __nv_bfloat16 lx = __float2bfloat16_rn(x - __bfloat162float(hx));
    __nv_bfloat16 ly = __float2bfloat16_rn(y - __bfloat162float(hy));
    __nv_bfloat162 h2 = __halves2bfloat162(hx, hy);
    __nv_bfloat162 l2 = __halves2bfloat162(lx, ly);
    hi = *(uint32_t*)&h2;
    lo = *(uint32_t*)&l2;
}

// ---------------- weight split kernel ----------------
__global__ __launch_bounds__(256) void split_kernel(
    const float2* __restrict__ src, uint32_t* __restrict__ hi,
    uint32_t* __restrict__ lo, int n2)
{
    int i = blockIdx.x * 256 + threadIdx.x;
    if (i < n2) {
        float2 v = src[i];
        uint32_t h, l;
        split2(v.x, v.y, h, l);
        hi[i] = h; lo[i] = l;
    }
}

// ---------------- block reduction (128 threads) ----------------
__device__ __forceinline__ float block_sum128(float v) {
    __shared__ float sm[4];
    #pragma unroll
    for (int o = 16; o; o >>= 1) v += __shfl_xor_sync(0xffffffffu, v, o);
    if ((threadIdx.x & 31) == 0) sm[threadIdx.x >> 5] = v;
    __syncthreads();
    float t = sm[0] + sm[1] + sm[2] + sm[3];
    __syncthreads();
    return t;
}

// ---------------- LayerNorm -> bf16 hi/lo planes ----------------
template<int D>
__global__ __launch_bounds__(128) void ln_split(
    const float* __restrict__ in, const float* __restrict__ w,
    const float* __restrict__ b, uint32_t* __restrict__ oh,
    uint32_t* __restrict__ ol)
{
    constexpr int V = D / 512;
    const size_t base = (size_t)blockIdx.x * D;
    float4 xv[V];
    float s = 0.f;
    #pragma unroll
    for (int j = 0; j < V; j++) {
        xv[j] = *(const float4*)(in + base + (size_t)(j * 128 + threadIdx.x) * 4);
        s += xv[j].x + xv[j].y + xv[j].z + xv[j].w;
    }
    const float mu = block_sum128(s) * (1.f / D);
    float vs = 0.f;
    #pragma unroll
    for (int j = 0; j < V; j++) {
        float dx = xv[j].x - mu, dy = xv[j].y - mu, dz = xv[j].z - mu, dw = xv[j].w - mu;
        vs += dx*dx + dy*dy + dz*dz + dw*dw;
    }
    const float var = block_sum128(vs) * (1.f / D);
    const float rs = rsqrtf(var + EPS_LN);
    #pragma unroll
    for (int j = 0; j < V; j++) {
        int idx = (j * 128 + threadIdx.x) * 4;
        float4 wv = *(const float4*)(w + idx);
        float4 bv = *(const float4*)(b + idx);
        float o0 = (xv[j].x - mu) * rs * wv.x + bv.x;
        float o1 = (xv[j].y - mu) * rs * wv.y + bv.y;
        float o2 = (xv[j].z - mu) * rs * wv.z + bv.z;
        float o3 = (xv[j].w - mu) * rs * wv.w + bv.w;
        uint32_t h0, l0, h1, l1;
        split2(o0, o1, h0, l0);
        split2(o2, o3, h1, l1);
        size_t u = (base + idx) >> 1;
        oh[u] = h0; oh[u+1] = h1;
        ol[u] = l0; ol[u+1] = l1;
    }
}

// ---------------- fused: h = LN(a)+x (fp32) ; z = LN(h) (bf16 hi/lo) ----------------
__global__ __launch_bounds__(128) void hz_kernel(
    const float* __restrict__ a, const float* __restrict__ x,
    const float* __restrict__ n2w, const float* __restrict__ n2b,
    const float* __restrict__ m1w, const float* __restrict__ m1b,
    float* __restrict__ h, uint32_t* __restrict__ zh, uint32_t* __restrict__ zl)
{
    const size_t base = (size_t)blockIdx.x * EMBED;
    const int t4 = threadIdx.x * 4;
    float4 av = *(const float4*)(a + base + t4);
    float4 xv = *(const float4*)(x + base + t4);

    float s = av.x + av.y + av.z + av.w;
    float mu = block_sum128(s) * (1.f / EMBED);
    float dx = av.x-mu, dy = av.y-mu, dz = av.z-mu, dw = av.w-mu;
    float var = block_sum128(dx*dx+dy*dy+dz*dz+dw*dw) * (1.f / EMBED);
    float rs = rsqrtf(var + EPS_LN);
    float4 wv = *(const float4*)(n2w + t4);
    float4 bv = *(const float4*)(n2b + t4);
    float4 hv;
    hv.x = dx * rs * wv.x + bv.x + xv.x;
    hv.y = dy * rs * wv.y + bv.y + xv.y;
    hv.z = dz * rs * wv.z + bv.z + xv.z;
    hv.w = dw * rs * wv.w + bv.w + xv.w;
    *(float4*)(h + base + t4) = hv;

    s = hv.x + hv.y + hv.z + hv.w;
    float mu2 = block_sum128(s) * (1.f / EMBED);
    dx = hv.x-mu2; dy = hv.y-mu2; dz = hv.z-mu2; dw = hv.w-mu2;
    float var2 = block_sum128(dx*dx+dy*dy+dz*dz+dw*dw) * (1.f / EMBED);
    float rs2 = rsqrtf(var2 + EPS_LN);
    float4 w2 = *(const float4*)(m1w + t4);
    float4 b2 = *(const float4*)(m1b + t4);
    float z0 = dx * rs2 * w2.x + b2.x;
    float z1 = dy * rs2 * w2.y + b2.y;
    float z2 = dz * rs2 * w2.z + b2.z;
    float z3 = dw * rs2 * w2.w + b2.w;
    uint32_t h0, l0, h1, l1;
    split2(z0, z1, h0, l0);
    split2(z2, z3, h1, l1);
    size_t u = (base + t4) >> 1;
    zh[u] = h0; zh[u+1] = h1;
    zl[u] = l0; zl[u+1] = l1;
}

// ---------------- bf16x3 tensor-core GEMM, pre-split inputs, cp.async 2-stage ----------------
// C[M,N] = A[M,K] @ W[N,K]^T, A/W given as packed-bf16x2 hi/lo planes.
// D = Ah*Bh + Ah*Bl + Al*Bh (fp32 acc). EPI: 0 plain, 1 bias+GELU, 2 bias+res.
// 128x128 tile, BK=32, 256 threads (2x4 warps, warp tile 64x32).

__device__ __forceinline__ void mma16816(float d[4],
    uint32_t a0, uint32_t a1, uint32_t a2, uint32_t a3,
    uint32_t b0, uint32_t b1)
{
    asm volatile(
        "mma.sync.aligned.m16n8k16.row.col.f32.bf16.bf16.f32 "
        "{%0,%1,%2,%3}, {%4,%5,%6,%7}, {%8,%9}, {%0,%1,%2,%3};\n"
        : "+f"(d[0]), "+f"(d[1]), "+f"(d[2]), "+f"(d[3])
        : "r"(a0), "r"(a1), "r"(a2), "r"(a3), "r"(b0), "r"(b1));
}

__device__ __forceinline__ uint32_t smem_u32(const void* p) {
    uint32_t a;
    asm("{ .reg .u64 t; cvta.to.shared.u64 t, %1; cvt.u32.u64 %0, t; }"
        : "=r"(a) : "l"(p));
    return a;
}

#define GS_ARR   2560            // uint32 per array (128 rows * 20 stride)
#define GS_STAGE (4*GS_ARR)      // uint32 per stage
#define GEMM_SMEM (2*GS_STAGE*4) // bytes (81920)

template<int EPI>
__global__ __launch_bounds__(256) void bf_gemm(
    const uint32_t* __restrict__ Ah, const uint32_t* __restrict__ Al,
    const uint32_t* __restrict__ Bh, const uint32_t* __restrict__ Bl,
    const float* __restrict__ bias, const float* __restrict__ res,
    float* __restrict__ C, int M, int N, int K)
{
    extern __shared__ uint32_t smg[];
    const int tid = threadIdx.x;
    const int lane = tid & 31, warp = tid >> 5;
    const int wm = warp >> 2, wn = warp & 3;
    const int lq = lane >> 2, lr = lane & 3;
    const int row0 = blockIdx.y * 128, col0 = blockIdx.x * 128;
    const int K2 = K >> 1;                 // uint32 per row
    const uint32_t sbase = smem_u32(smg);

    // per-thread load geometry (fixed across k): e -> arr = e>>1,
    // r = (e&1)*64 + tid>>2, c16 = tid&3
    const int lrr = tid >> 2, lc16 = tid & 3;

    float acc[4][4][4];
    #pragma unroll
    for (int i = 0; i < 4; i++)
        #pragma unroll
        for (int j = 0; j < 4; j++)
            #pragma unroll
            for (int t = 0; t < 4; t++) acc[i][j][t] = 0.f;

    const uint32_t* gp[4] = {Ah, Al, Bh, Bl};

    const int NS = K >> 5;
    // ---- issue stage macro ----
    #define ISSUE_STAGE(S, K0) do {                                          \
        uint32_t sb = sbase + (S) * (GS_STAGE * 4);                          \
        _Pragma("unroll")                                                    \
        for (int e = 0; e < 8; e++) {                                        \
            const int arr = e >> 1;                                          \
            const int r = ((e & 1) << 6) + lrr;                              \
            const int grow = (arr < 2 ? row0 : col0) + r;                    \
            const uint32_t* src = gp[arr] + (size_t)grow * K2 + ((K0) >> 1) + lc16 * 4; \
            uint32_t dst = sb + (arr * GS_ARR + r * 20 + lc16 * 4) * 4;      \
            asm volatile("cp.async.cg.shared.global [%0], [%1], 16;\n"       \
                         :: "r"(dst), "l"(src));                             \
        }                                                                    \
        asm volatile("cp.async.commit_group;\n");                            \
    } while (0)

    ISSUE_STAGE(0, 0);

    for (int kslab = 0; kslab < NS; kslab++) {
        if (kslab + 1 < NS) {
            ISSUE_STAGE((kslab + 1) & 1, (kslab + 1) << 5);
            asm volatile("cp.async.wait_group 1;\n");
        } else {
            asm volatile("cp.async.wait_group 0;\n");
        }
        __syncthreads();

        const uint32_t* AsH = smg + (kslab & 1) * GS_STAGE;
        const uint32_t* AsL = AsH + GS_ARR;
        const uint32_t* BsH = AsH + 2 * GS_ARR;
        const uint32_t* BsL = AsH + 3 * GS_ARR;

        #pragma unroll
        for (int ks = 0; ks < 2; ks++) {
            const int kw = ks * 8;
            uint32_t ah[4][4], al[4][4], bh[4][2], bl[4][2];
            #pragma unroll
            for (int mf = 0; mf < 4; mf++) {
                int aw = (wm * 64 + mf * 16 + lq) * 20 + kw + lr;
                ah[mf][0] = AsH[aw];       ah[mf][1] = AsH[aw + 160];
                ah[mf][2] = AsH[aw + 4];   ah[mf][3] = AsH[aw + 164];
                al[mf][0] = AsL[aw];       al[mf][1] = AsL[aw + 160];
                al[mf][2] = AsL[aw + 4];   al[mf][3] = AsL[aw + 164];
            }
            #pragma unroll
            for (int nf = 0; nf < 4; nf++) {
                int bw = (wn * 32 + nf * 8 + lq) * 20 + kw + lr;
                bh[nf][0] = BsH[bw];  bh[nf][1] = BsH[bw + 4];
                bl[nf][0] = BsL[bw];  bl[nf][1] = BsL[bw + 4];
            }
            #pragma unroll
            for (int mf = 0; mf < 4; mf++)
                #pragma unroll
                for (int nf = 0; nf < 4; nf++) {
                    mma16816(acc[mf][nf], ah[mf][0], ah[mf][1], ah[mf][2], ah[mf][3],
                             bh[nf][0], bh[nf][1]);
                    mma16816(acc[mf][nf], ah[mf][0], ah[mf][1], ah[mf][2], ah[mf][3],
                             bl[nf][0], bl[nf][1]);
                    mma16816(acc[mf][nf], al[mf][0], al[mf][1], al[mf][2], al[mf][3],
                             bh[nf][0], bh[nf][1]);
                }
        }
        __syncthreads();
    }
    #undef ISSUE_STAGE

    // epilogue
    #pragma unroll
    for (int mf = 0; mf < 4; mf++) {
        #pragma unroll
        for (int nf = 0; nf < 4; nf++) {
            int row = row0 + wm * 64 + mf * 16 + lq;
            int col = col0 + wn * 32 + nf * 8 + lr * 2;
            #pragma unroll
            for (int half = 0; half < 2; half++) {
                int rr = row + half * 8;
                float v0 = acc[mf][nf][half * 2 + 0];
                float v1 = acc[mf][nf][half * 2 + 1];
                if (EPI == 1) {
                    v0 += bias[col];     v1 += bias[col + 1];
                    v0 = 0.5f * v0 * (1.f + erff(v0 * 0.70710678118654752f));
                    v1 = 0.5f * v1 * (1.f + erff(v1 * 0.70710678118654752f));
                } else if (EPI == 2) {
                    v0 += bias[col]     + res[(size_t)rr * N + col];
                    v1 += bias[col + 1] + res[(size_t)rr * N + col + 1];
                }
                *(float2*)(C + (size_t)rr * N + col) = make_float2(v0, v1);
            }
        }
    }
}

// ---------------- differential flash attention (register-tiled) ----------------
extern __shared__ float sm_attn[];
#define PS 68

__global__ __launch_bounds__(256) void attn_kernel(
    const float* __restrict__ q, const float* __restrict__ k, const float* __restrict__ v,
    const float* __restrict__ lq1, const float* __restrict__ lk1,
    const float* __restrict__ lq2, const float* __restrict__ lk2,
    const float* __restrict__ subw, uint32_t* __restrict__ aoh, uint32_t* __restrict__ aol)
{
    float* sQ0 = sm_attn;
    float* sQ1 = sQ0 + 32*PS;
    float* sK0 = sQ1 + 32*PS;
    float* sK1 = sK0 + 32*PS;
    float* sS0 = sK1 + 32*PS;
    float* sS1 = sS0 + 64*PS;
    float* sV  = sS1 + 64*PS;
    float* sF0 = sV  + 64*PS;
    float* sF1 = sF0 + 64;
    float* sL0 = sF1 + 64;
    float* sL1 = sL0 + 64;
    __shared__ float s_lam;

    const int tid = threadIdx.x;
    const int qt = blockIdx.x, h = blockIdx.y, b = blockIdx.z;

    if (tid == 0) {
        float s1 = 0.f, s2 = 0.f;
        #pragma unroll
        for (int i = 0; i < HD; i++) { s1 += lq1[i]*lk1[i]; s2 += lq2[i]*lk2[i]; }
        s_lam = expf(s1) - expf(s2) + LAMBDA_INIT;
    }

    const float scale = 0.17677669529663687f * 1.4426950408889634f;

    #pragma unroll
    for (int e = 0; e < 4; e++) {
        int lin = tid + e * 256;
        int head = lin >> 9;
        int rem = lin & 511;
        int row = rem >> 3;
        int c4 = (rem & 7) << 2;
        float4 qv = *(const float4*)(q + ((size_t)(b*SEQ + qt*64 + row))*EMBED + (2*h + head)*HD + c4);
        float* dst = head ? sQ1 : sQ0;
        dst[(c4+0)*PS + row] = qv.x*scale;
        dst[(c4+1)*PS + row] = qv.y*scale;
        dst[(c4+2)*PS + row] = qv.z*scale;
        dst[(c4+3)*PS + row] = qv.w*scale;
    }

    const int ty = tid >> 4, tx = tid & 15;
    const int sr = tid >> 2, spart = tid & 3;

    float m0 = -1e30f, m1 = -1e30f, l0 = 0.f, l1 = 0.f;
    float acc0[4][4], acc1[4][4];
    #pragma unroll
    for (int i = 0; i < 4; i++)
        #pragma unroll
        for (int j = 0; j < 4; j++) { acc0[i][j] = 0.f; acc1[i][j] = 0.f; }

    for (int kt = 0; kt < SEQ/64; kt++) {
        __syncthreads();
        #pragma unroll
        for (int e = 0; e < 4; e++) {
            int lin = tid + e * 256;
            int head = lin >> 9;
            int rem = lin & 511;
            int row = rem >> 3;
            int c4 = (rem & 7) << 2;
            float4 kv = *(const float4*)(k + ((size_t)(b*SEQ + kt*64 + row))*EMBED + (2*h + head)*HD + c4);
            float* dst = head ? sK1 : sK0;
            dst[(c4+0)*PS + row] = kv.x;
            dst[(c4+1)*PS + row] = kv.y;
            dst[(c4+2)*PS + row] = kv.z;
            dst[(c4+3)*PS + row] = kv.w;
        }
        #pragma unroll
        for (int e = 0; e < 4; e++) {
            int lin = tid + e * 256;
            int row = lin >> 4;
            int c4 = (lin & 15) << 2;
            float4 vv = *(const float4*)(v + ((size_t)(b*SEQ + kt*64 + row))*EMBED + h*VD + c4);
            *(float4*)(sV + row*PS + c4) = vv;
        }
        __syncthreads();

        {
            float s0a[4][4], s1a[4][4];
            #pragma unroll
            for (int i = 0; i < 4; i++)
                #pragma unroll
                for (int j = 0; j < 4; j++) { s0a[i][j] = 0.f; s1a[i][j] = 0.f; }
            #pragma unroll 8
            for (int kk = 0; kk < 32; kk++) {
                float4 a0 = *(const float4*)(sQ0 + kk*PS + ty*4);
                float4 a1 = *(const float4*)(sQ1 + kk*PS + ty*4);
                float4 b0 = *(const float4*)(sK0 + kk*PS + tx*4);
                float4 b1 = *(const float4*)(sK1 + kk*PS + tx*4);
                float aa0[4] = {a0.x,a0.y,a0.z,a0.w};
                float aa1[4] = {a1.x,a1.y,a1.z,a1.w};
                float bb0[4] = {b0.x,b0.y,b0.z,b0.w};
                float bb1[4] = {b1.x,b1.y,b1.z,b1.w};
                #pragma unroll
                for (int i = 0; i < 4; i++)
                    #pragma unroll
                    for (int j = 0; j < 4; j++) {
                        s0a[i][j] += aa0[i]*bb0[j];
                        s1a[i][j] += aa1[i]*bb1[j];
                    }
            }
            #pragma unroll
            for (int i = 0; i < 4; i++)
                #pragma unroll
                for (int j = 0; j < 4; j++) {
                    sS0[(ty*4+i)*PS + tx*4+j] = s0a[i][j];
                    sS1[(ty*4+i)*PS + tx*4+j] = s1a[i][j];
                }
        }
        __syncthreads();

        {
            float v0[16], v1[16];
            float tm0 = -1e30f, tm1 = -1e30f;
            #pragma unroll
            for (int c4 = 0; c4 < 4; c4++) {
                float4 f0 = *(const float4*)(sS0 + sr*PS + spart*16 + c4*4);
                float4 f1 = *(const float4*)(sS1 + sr*PS + spart*16 + c4*4);
                v0[c4*4+0]=f0.x; v0[c4*4+1]=f0.y; v0[c4*4+2]=f0.z; v0[c4*4+3]=f0.w;
                v1[c4*4+0]=f1.x; v1[c4*4+1]=f1.y; v1[c4*4+2]=f1.z; v1[c4*4+3]=f1.w;
                tm0 = fmaxf(tm0, fmaxf(fmaxf(f0.x,f0.y), fmaxf(f0.z,f0.w)));
                tm1 = fmaxf(tm1, fmaxf(fmaxf(f1.x,f1.y), fmaxf(f1.z,f1.w)));
            }
            #pragma unroll
            for (int o = 1; o < 4; o <<= 1) {
                tm0 = fmaxf(tm0, __shfl_xor_sync(0xffffffffu, tm0, o));
                tm1 = fmaxf(tm1, __shfl_xor_sync(0xffffffffu, tm1, o));
            }
            const float nm0 = fmaxf(m0, tm0), nm1 = fmaxf(m1, tm1);
            const float f0 = exp2f(m0 - nm0), f1 = exp2f(m1 - nm1);
            float ps0 = 0.f, ps1 = 0.f;
            #pragma unroll
            for (int c = 0; c < 16; c++) {
                v0[c] = exp2f(v0[c] - nm0);
                v1[c] = exp2f(v1[c] - nm1);
                ps0 += v0[c]; ps1 += v1[c];
            }
            #pragma unroll
            for (int c4 = 0; c4 < 4; c4++) {
                *(float4*)(sS0 + sr*PS + spart*16 + c4*4) =
                    make_float4(v0[c4*4+0], v0[c4*4+1], v0[c4*4+2], v0[c4*4+3]);
                *(float4*)(sS1 + sr*PS + spart*16 + c4*4) =
                    make_float4(v1[c4*4+0], v1[c4*4+1], v1[c4*4+2], v1[c4*4+3]);
            }
            #pragma unroll
            for (int o = 1; o < 4; o <<= 1) {
                ps0 += __shfl_xor_sync(0xffffffffu, ps0, o);
                ps1 += __shfl_xor_sync(0xffffffffu, ps1, o);
            }
            l0 = l0 * f0 + ps0; l1 = l1 * f1 + ps1;
            m0 = nm0; m1 = nm1;
            if (spart == 0) {
                sF0[sr] = f0; sF1[sr] = f1;
                sL0[sr] = l0; sL1[sr] = l1;
            }
        }
        __syncthreads();

        {
            float f0r[4], f1r[4];
            #pragma unroll
            for (int i = 0; i < 4; i++) { f0r[i] = sF0[ty*4+i]; f1r[i] = sF1[ty*4+i]; }
            #pragma unroll
            for (int i = 0; i < 4; i++)
                #pragma unroll
                for (int j = 0; j < 4; j++) { acc0[i][j] *= f0r[i]; acc1[i][j] *= f1r[i]; }
            #pragma unroll 8
            for (int jk = 0; jk < 64; jk++) {
                float4 vv = *(const float4*)(sV + jk*PS + tx*4);
                float vva[4] = {vv.x, vv.y, vv.z, vv.w};
                float p0[4], p1[4];
                #pragma unroll
                for (int i = 0; i < 4; i++) {
                    p0[i] = sS0[(ty*4+i)*PS + jk];
                    p1[i] = sS1[(ty*4+i)*PS + jk];
                }
                #pragma unroll
                for (int i = 0; i < 4; i++)
                    #pragma unroll
                    for (int j = 0; j < 4; j++) {
                        acc0[i][j] += p0[i]*vva[j];
                        acc1[i][j] += p1[i]*vva[j];
                    }
            }
        }
    }

    // epilogue: combine, rmsnorm(64), write bf16 hi/lo
    const float lam = s_lam;
    float linv0[4], linv1[4];
    #pragma unroll
    for (int i = 0; i < 4; i++) {
        linv0[i] = 1.f / sL0[ty*4+i];
        linv1[i] = 1.f / sL1[ty*4+i];
    }
    float o[4][4], ss[4];
    #pragma unroll
    for (int i = 0; i < 4; i++) {
        ss[i] = 0.f;
        #pragma unroll
        for (int j = 0; j < 4; j++) {
            o[i][j] = acc0[i][j]*linv0[i] - lam*acc1[i][j]*linv1[i];
            ss[i] += o[i][j]*o[i][j];
        }
    }
    #pragma unroll
    for (int i = 0; i < 4; i++)
        #pragma unroll
        for (int off = 1; off < 16; off <<= 1)
            ss[i] += __shfl_xor_sync(0xffffffffu, ss[i], off);
    float4 wv = *(const float4*)(subw + tx*4);
    float wva[4] = {wv.x, wv.y, wv.z, wv.w};
    #pragma unroll
    for (int i = 0; i < 4; i++) {
        const float rsn = rsqrtf(ss[i] * (1.f / VD) + EPS_LN) * (1.f - LAMBDA_INIT);
        float o0 = o[i][0]*rsn*wva[0];
        float o1 = o[i][1]*rsn*wva[1];
        float o2 = o[i][2]*rsn*wva[2];
        float o3 = o[i][3]*rsn*wva[3];
        uint32_t h0, l0u, h1, l1u;
        split2(o0, o1, h0, l0u);
        split2(o2, o3, h1, l1u);
        size_t u = (((size_t)(b*SEQ + qt*64 + ty*4 + i))*EMBED + h*VD + tx*4) >> 1;
        aoh[u] = h0; aoh[u+1] = h1;
        aol[u] = l0u; aol[u+1] = l1u;
    }
}

#define ATTN_SMEM ((4*32*PS + 2*64*PS + 64*PS + 4*64) * (int)sizeof(float))

// ---------------- host launch ----------------
extern "C" void kernel_launch(void* const* d_in, const int* in_sizes, int n_in,
                              void* d_out, int out_size)
{
    (void)in_sizes; (void)n_in; (void)out_size;
    const float* x     = (const float*)d_in[0];
    const float* Wq    = (const float*)d_in[1];
    const float* Wk    = (const float*)d_in[2];
    const float* Wv    = (const float*)d_in[3];
    const float* Wo    = (const float*)d_in[4];
    const float* lq1   = (const float*)d_in[5];
    const float* lk1   = (const float*)d_in[6];
    const float* lq2   = (const float*)d_in[7];
    const float* lk2   = (const float*)d_in[8];
    const float* subw  = (const float*)d_in[9];
    const float* n1w   = (const float*)d_in[10];
    const float* n1b   = (const float*)d_in[11];
    const float* n2w   = (const float*)d_in[12];
    const float* n2b   = (const float*)d_in[13];
    const float* mln1w = (const float*)d_in[14];
    const float* mln1b = (const float*)d_in[15];
    const float* mW1   = (const float*)d_in[16];
    const float* mb1   = (const float*)d_in[17];
    const float* mln2w = (const float*)d_in[18];
    const float* mln2b = (const float*)d_in[19];
    const float* mW2   = (const float*)d_in[20];
    const float* mb2   = (const float*)d_in[21];
    float* out = (float*)d_out;

    float *qb, *kb, *vb, *ab, *hb, *z1;
    uint32_t *xnh, *xnl, *aoh, *aol, *z2h, *z2l;
    uint32_t *wqh, *wql, *wkh, *wkl, *wvh, *wvl, *woh, *wol, *w1h, *w1l, *w2h, *w2l;
    cudaGetSymbolAddress((void**)&qb, g_q);
    cudaGetSymbolAddress((void**)&kb, g_k);
    cudaGetSymbolAddress((void**)&vb, g_v);
    cudaGetSymbolAddress((void**)&ab, g_ab);
    cudaGetSymbolAddress((void**)&hb, g_h);
    cudaGetSymbolAddress((void**)&z1, g_z1);
    cudaGetSymbolAddress((void**)&xnh, g_xnh);
    cudaGetSymbolAddress((void**)&xnl, g_xnl);
    cudaGetSymbolAddress((void**)&aoh, g_aoh);
    cudaGetSymbolAddress((void**)&aol, g_aol);
    cudaGetSymbolAddress((void**)&z2h, g_z2h);
    cudaGetSymbolAddress((void**)&z2l, g_z2l);
    cudaGetSymbolAddress((void**)&wqh, g_wqh);
    cudaGetSymbolAddress((void**)&wql, g_wql);
    cudaGetSymbolAddress((void**)&wkh, g_wkh);
    cudaGetSymbolAddress((void**)&wkl, g_wkl);
    cudaGetSymbolAddress((void**)&wvh, g_wvh);
    cudaGetSymbolAddress((void**)&wvl, g_wvl);
    cudaGetSymbolAddress((void**)&woh, g_woh);
    cudaGetSymbolAddress((void**)&wol, g_wol);
    cudaGetSymbolAddress((void**)&w1h, g_w1h);
    cudaGetSymbolAddress((void**)&w1l, g_w1l);
    cudaGetSymbolAddress((void**)&w2h, g_w2h);
    cudaGetSymbolAddress((void**)&w2l, g_w2l);

    static bool attr_set = false;
    if (!attr_set) {
        cudaFuncSetAttribute(attn_kernel,
            cudaFuncAttributeMaxDynamicSharedMemorySize, ATTN_SMEM);
        cudaFuncSetAttribute(bf_gemm<0>,
            cudaFuncAttributeMaxDynamicSharedMemorySize, GEMM_SMEM);
        cudaFuncSetAttribute(bf_gemm<1>,
            cudaFuncAttributeMaxDynamicSharedMemorySize, GEMM_SMEM);
        cudaFuncSetAttribute(bf_gemm<2>,
            cudaFuncAttributeMaxDynamicSharedMemorySize, GEMM_SMEM);
        attr_set = true;
    }

    // 0. split weights into bf16 hi/lo planes
    const int nw = EMBED*EMBED/2, nm = EXPD*EMBED/2;
    split_kernel<<<(nw+255)/256, 256>>>((const float2*)Wq, wqh, wql, nw);
    split_kernel<<<(nw+255)/256, 256>>>((const float2*)Wk, wkh, wkl, nw);
    split_kernel<<<(nw+255)/256, 256>>>((const float2*)Wv, wvh, wvl, nw);
    split_kernel<<<(nw+255)/256, 256>>>((const float2*)Wo, woh, wol, nw);
    split_kernel<<<(nm+255)/256, 256>>>((const float2*)mW1, w1h, w1l, nm);
    split_kernel<<<(nm+255)/256, 256>>>((const float2*)mW2, w2h, w2l, nm);

    const dim3 g512(EMBED/128, BN/128);   // (4, 64)
    const dim3 g2048(EXPD/128, BN/128);   // (16, 64)

    // 1. xn = LN(x) -> bf16 hi/lo
    ln_split<EMBED><<<BN, 128>>>(x, n1w, n1b, xnh, xnl);
    // 2. q/k/v = xn @ W^T
    bf_gemm<0><<<g512, 256, GEMM_SMEM>>>(xnh, xnl, wqh, wql, nullptr, nullptr, qb, BN, EMBED, EMBED);
    bf_gemm<0><<<g512, 256, GEMM_SMEM>>>(xnh, xnl, wkh, wkl, nullptr, nullptr, kb, BN, EMBED, EMBED);
    bf_gemm<0><<<g512, 256, GEMM_SMEM>>>(xnh, xnl, wvh, wvl, nullptr, nullptr, vb, BN, EMBED, EMBED);
    // 3. differential attention -> ao bf16 hi/lo
    attn_kernel<<<dim3(SEQ/64, HEADS, BATCH), 256, ATTN_SMEM>>>(
        qb, kb, vb, lq1, lk1, lq2, lk2, subw, aoh, aol);
    // 4. a = ao @ Wo^T (fp32)
    bf_gemm<0><<<g512, 256, GEMM_SMEM>>>(aoh, aol, woh, wol, nullptr, nullptr, ab, BN, EMBED, EMBED);
    // 5. h = LN(a)+x (fp32) ; z = LN(h) (bf16 hi/lo)
    hz_kernel<<<BN, 128>>>(ab, x, n2w, n2b, mln1w, mln1b, hb, xnh, xnl);
    // 6. z1 = GELU(z @ mW1^T + mb1) (fp32)
    bf_gemm<1><<<g2048, 256, GEMM_SMEM>>>(xnh, xnl, w1h, w1l, mb1, nullptr, z1, BN, EXPD, EMBED);
    // 7. z2 = LN(z1) -> bf16 hi/lo
    ln_split<EXPD><<<BN, 128>>>(z1, mln2w, mln2b, z2h, z2l);
    // 8. out = z2 @ mW2^T + mb2 + h
    bf_gemm<2><<<g512, 256, GEMM_SMEM>>>(z2h, z2l, w2h, w2l, mb2, hb, out, BN, EMBED, EXPD);
}

// round 9
// speedup vs baseline: 5.7500x; 1.0016x over previous
#include <cuda_runtime.h>
#include <cuda_bf16.h>
#include <math.h>
#include <stdint.h>

// ---------------- problem constants ----------------
#define BATCH 8
#define SEQ   1024
#define EMBED 512
#define BN    (BATCH*SEQ)          // 8192
#define HEADS 8
#define HD    32
#define VD    64
#define EXPD  2048
#define LAMBDA_INIT 0.2f
#define EPS_LN 1e-5f

// ---------------- device scratch ----------------
__device__ float g_q [(size_t)BN*EMBED];
__device__ float g_k [(size_t)BN*EMBED];
__device__ float g_v [(size_t)BN*EMBED];
__device__ float g_ab[(size_t)BN*EMBED];
__device__ float g_h [(size_t)BN*EMBED];
__device__ float g_z1[(size_t)BN*EXPD];
// packed bf16x2 planes (hi/lo)
__device__ uint32_t g_xnh[(size_t)BN*EMBED/2], g_xnl[(size_t)BN*EMBED/2];
__device__ uint32_t g_aoh[(size_t)BN*EMBED/2], g_aol[(size_t)BN*EMBED/2];
__device__ uint32_t g_z2h[(size_t)BN*EXPD/2],  g_z2l[(size_t)BN*EXPD/2];
__device__ uint32_t g_wqh[EMBED*EMBED/2], g_wql[EMBED*EMBED/2];
__device__ uint32_t g_wkh[EMBED*EMBED/2], g_wkl[EMBED*EMBED/2];
__device__ uint32_t g_wvh[EMBED*EMBED/2], g_wvl[EMBED*EMBED/2];
__device__ uint32_t g_woh[EMBED*EMBED/2], g_wol[EMBED*EMBED/2];
__device__ uint32_t g_w1h[EXPD*EMBED/2],  g_w1l[EXPD*EMBED/2];
__device__ uint32_t g_w2h[EMBED*EXPD/2],  g_w2l[EMBED*EXPD/2];

__device__ __forceinline__ void split2(float x, float y, uint32_t& hi, uint32_t& lo) {
    __nv_bfloat16 hx = __float2bfloat16_rn(x);
    __nv_bfloat16 hy = __float2bfloat16_rn(y);
    __nv_bfloat16 lx = __float2bfloat16_rn(x - __bfloat162float(hx));
    __nv_bfloat16 ly = __float2bfloat16_rn(y - __bfloat162float(hy));
    __nv_bfloat162 h2 = __halves2bfloat162(hx, hy);
    __nv_bfloat162 l2 = __halves2bfloat162(lx, ly);
    hi = *(uint32_t*)&h2;
    lo = *(uint32_t*)&l2;
}

// ---------------- combined weight split kernel (all 6 weights in one launch) ----------------
__global__ __launch_bounds__(256) void split_all(
    const float2* __restrict__ s0, uint32_t* __restrict__ h0, uint32_t* __restrict__ l0, int n0,
    const float2* __restrict__ s1, uint32_t* __restrict__ h1, uint32_t* __restrict__ l1, int n1,
    const float2* __restrict__ s2, uint32_t* __restrict__ h2, uint32_t* __restrict__ l2, int n2,
    const float2* __restrict__ s3, uint32_t* __restrict__ h3, uint32_t* __restrict__ l3, int n3,
    const float2* __restrict__ s4, uint32_t* __restrict__ h4, uint32_t* __restrict__ l4, int n4,
    const float2* __restrict__ s5, uint32_t* __restrict__ h5, uint32_t* __restrict__ l5, int n5)
{
    const float2* src; uint32_t *hp, *lp; int n;
    switch (blockIdx.y) {
        case 0: src = s0; hp = h0; lp = l0; n = n0; break;
        case 1: src = s1; hp = h1; lp = l1; n = n1; break;
        case 2: src = s2; hp = h2; lp = l2; n = n2; break;
        case 3: src = s3; hp = h3; lp = l3; n = n3; break;
        case 4: src = s4; hp = h4; lp = l4; n = n4; break;
        default: src = s5; hp = h5; lp = l5; n = n5; break;
    }
    int i = blockIdx.x * 256 + threadIdx.x;
    if (i < n) {
        float2 v = src[i];
        uint32_t h, l;
        split2(v.x, v.y, h, l);
        hp[i] = h; lp[i] = l;
    }
}

// ---------------- block reduction (128 threads) ----------------
__device__ __forceinline__ float block_sum128(float v) {
    __shared__ float sm[4];
    #pragma unroll
    for (int o = 16; o; o >>= 1) v += __shfl_xor_sync(0xffffffffu, v, o);
    if ((threadIdx.x & 31) == 0) sm[threadIdx.x >> 5] = v;
    __syncthreads();
    float t = sm[0] + sm[1] + sm[2] + sm[3];
    __syncthreads();
    return t;
}

// ---------------- LayerNorm -> bf16 hi/lo planes ----------------
template<int D>
__global__ __launch_bounds__(128) void ln_split(
    const float* __restrict__ in, const float* __restrict__ w,
    const float* __restrict__ b, uint32_t* __restrict__ oh,
    uint32_t* __restrict__ ol)
{
    constexpr int V = D / 512;
    const size_t base = (size_t)blockIdx.x * D;
    float4 xv[V];
    float s = 0.f;
    #pragma unroll
    for (int j = 0; j < V; j++) {
        xv[j] = *(const float4*)(in + base + (size_t)(j * 128 + threadIdx.x) * 4);
        s += xv[j].x + xv[j].y + xv[j].z + xv[j].w;
    }
    const float mu = block_sum128(s) * (1.f / D);
    float vs = 0.f;
    #pragma unroll
    for (int j = 0; j < V; j++) {
        float dx = xv[j].x - mu, dy = xv[j].y - mu, dz = xv[j].z - mu, dw = xv[j].w - mu;
        vs += dx*dx + dy*dy + dz*dz + dw*dw;
    }
    const float var = block_sum128(vs) * (1.f / D);
    const float rs = rsqrtf(var + EPS_LN);
    #pragma unroll
    for (int j = 0; j < V; j++) {
        int idx = (j * 128 + threadIdx.x) * 4;
        float4 wv = *(const float4*)(w + idx);
        float4 bv = *(const float4*)(b + idx);
        float o0 = (xv[j].x - mu) * rs * wv.x + bv.x;
        float o1 = (xv[j].y - mu) * rs * wv.y + bv.y;
        float o2 = (xv[j].z - mu) * rs * wv.z + bv.z;
        float o3 = (xv[j].w - mu) * rs * wv.w + bv.w;
        uint32_t h0, l0, h1, l1;
        split2(o0, o1, h0, l0);
        split2(o2, o3, h1, l1);
        size_t u = (base + idx) >> 1;
        oh[u] = h0; oh[u+1] = h1;
        ol[u] = l0; ol[u+1] = l1;
    }
}

// ---------------- fused: h = LN(a)+x (fp32) ; z = LN(h) (bf16 hi/lo) ----------------
__global__ __launch_bounds__(128) void hz_kernel(
    const float* __restrict__ a, const float* __restrict__ x,
    const float* __restrict__ n2w, const float* __restrict__ n2b,
    const float* __restrict__ m1w, const float* __restrict__ m1b,
    float* __restrict__ h, uint32_t* __restrict__ zh, uint32_t* __restrict__ zl)
{
    const size_t base = (size_t)blockIdx.x * EMBED;
    const int t4 = threadIdx.x * 4;
    float4 av = *(const float4*)(a + base + t4);
    float4 xv = *(const float4*)(x + base + t4);

    float s = av.x + av.y + av.z + av.w;
    float mu = block_sum128(s) * (1.f / EMBED);
    float dx = av.x-mu, dy = av.y-mu, dz = av.z-mu, dw = av.w-mu;
    float var = block_sum128(dx*dx+dy*dy+dz*dz+dw*dw) * (1.f / EMBED);
    float rs = rsqrtf(var + EPS_LN);
    float4 wv = *(const float4*)(n2w + t4);
    float4 bv = *(const float4*)(n2b + t4);
    float4 hv;
    hv.x = dx * rs * wv.x + bv.x + xv.x;
    hv.y = dy * rs * wv.y + bv.y + xv.y;
    hv.z = dz * rs * wv.z + bv.z + xv.z;
    hv.w = dw * rs * wv.w + bv.w + xv.w;
    *(float4*)(h + base + t4) = hv;

    s = hv.x + hv.y + hv.z + hv.w;
    float mu2 = block_sum128(s) * (1.f / EMBED);
    dx = hv.x-mu2; dy = hv.y-mu2; dz = hv.z-mu2; dw = hv.w-mu2;
    float var2 = block_sum128(dx*dx+dy*dy+dz*dz+dw*dw) * (1.f / EMBED);
    float rs2 = rsqrtf(var2 + EPS_LN);
    float4 w2 = *(const float4*)(m1w + t4);
    float4 b2 = *(const float4*)(m1b + t4);
    float z0 = dx * rs2 * w2.x + b2.x;
    float z1 = dy * rs2 * w2.y + b2.y;
    float z2 = dz * rs2 * w2.z + b2.z;
    float z3 = dw * rs2 * w2.w + b2.w;
    uint32_t h0, l0, h1, l1;
    split2(z0, z1, h0, l0);
    split2(z2, z3, h1, l1);
    size_t u = (base + t4) >> 1;
    zh[u] = h0; zh[u+1] = h1;
    zl[u] = l0; zl[u+1] = l1;
}

// ---------------- bf16x3 tensor-core GEMM, pre-split, cp.async 2-stage, ldmatrix ----------------
// C[M,N] = A[M,K] @ W[N,K]^T, inputs as packed-bf16x2 hi/lo planes.
// D = Ah*Bh + Ah*Bl + Al*Bh (fp32 acc). EPI: 0 plain, 1 bias+GELU, 2 bias+res.
// 128x128 tile, BK=32, 256 threads (2x4 warps, warp tile 64x32).

__device__ __forceinline__ void mma16816(float d[4],
    uint32_t a0, uint32_t a1, uint32_t a2, uint32_t a3,
    uint32_t b0, uint32_t b1)
{
    asm volatile(
        "mma.sync.aligned.m16n8k16.row.col.f32.bf16.bf16.f32 "
        "{%0,%1,%2,%3}, {%4,%5,%6,%7}, {%8,%9}, {%0,%1,%2,%3};\n"
        : "+f"(d[0]), "+f"(d[1]), "+f"(d[2]), "+f"(d[3])
        : "r"(a0), "r"(a1), "r"(a2), "r"(a3), "r"(b0), "r"(b1));
}

__device__ __forceinline__ void ldsm4(uint32_t& r0, uint32_t& r1,
                                      uint32_t& r2, uint32_t& r3, uint32_t addr)
{
    asm volatile("ldmatrix.sync.aligned.m8n8.x4.shared.b16 {%0,%1,%2,%3}, [%4];"
                 : "=r"(r0), "=r"(r1), "=r"(r2), "=r"(r3) : "r"(addr));
}

__device__ __forceinline__ uint32_t smem_u32(const void* p) {
    uint32_t a;
    asm("{ .reg .u64 t; cvta.to.shared.u64 t, %1; cvt.u32.u64 %0, t; }"
        : "=r"(a) : "l"(p));
    return a;
}

#define GS_ARR   2560            // uint32 per array (128 rows * 20 stride)
#define GS_STAGE (4*GS_ARR)      // uint32 per stage
#define GEMM_SMEM (2*GS_STAGE*4) // bytes (81920)

template<int EPI>
__global__ __launch_bounds__(256) void bf_gemm(
    const uint32_t* __restrict__ Ah, const uint32_t* __restrict__ Al,
    const uint32_t* __restrict__ Bh, const uint32_t* __restrict__ Bl,
    const float* __restrict__ bias, const float* __restrict__ res,
    float* __restrict__ C, int M, int N, int K)
{
    extern __shared__ uint32_t smg[];
    const int tid = threadIdx.x;
    const int lane = tid & 31, warp = tid >> 5;
    const int wm = warp >> 2, wn = warp & 3;
    const int lq = lane >> 2, lr = lane & 3;
    const int row0 = blockIdx.y * 128, col0 = blockIdx.x * 128;
    const int K2 = K >> 1;
    const uint32_t sbase = smem_u32(smg);

    const int lrr = tid >> 2, lc16 = tid & 3;

    // ldmatrix per-lane byte offsets (within a stage)
    // A tiles (m16xk16): lanes 0-15 -> rows 0-15, lanes 16-31 -> same rows, k+16B
    uint32_t aoffs[4], boffs[2];
    #pragma unroll
    for (int mf = 0; mf < 4; mf++)
        aoffs[mf] = (uint32_t)(((wm*64 + mf*16 + (lane & 15)) * 20 + ((lane >> 4) << 2)) << 2);
    // B tile pairs (n8xk16 x2): lanes 0-7 rows n0-7 k0 | 8-15 rows n0-7 k+16B
    //                           | 16-23 rows n8-15 k0 | 24-31 rows n8-15 k+16B
    #pragma unroll
    for (int p = 0; p < 2; p++)
        boffs[p] = (uint32_t)(((wn*32 + p*16 + (lane & 7) + (((lane >> 4) & 1) << 3)) * 20
                              + (((lane >> 3) & 1) << 2)) << 2);

    float acc[4][4][4];
    #pragma unroll
    for (int i = 0; i < 4; i++)
        #pragma unroll
        for (int j = 0; j < 4; j++)
            #pragma unroll
            for (int t = 0; t < 4; t++) acc[i][j][t] = 0.f;

    const uint32_t* gp[4] = {Ah, Al, Bh, Bl};
    const int NS = K >> 5;

    #define ISSUE_STAGE(S, K0) do {                                          \
        uint32_t sb = sbase + (S) * (GS_STAGE * 4);                          \
        _Pragma("unroll")                                                    \
        for (int e = 0; e < 8; e++) {                                        \
            const int arr = e >> 1;                                          \
            const int r = ((e & 1) << 6) + lrr;                              \
            const int grow = (arr < 2 ? row0 : col0) + r;                    \
            const uint32_t* src = gp[arr] + (size_t)grow * K2 + ((K0) >> 1) + lc16 * 4; \
            uint32_t dst = sb + (arr * GS_ARR + r * 20 + lc16 * 4) * 4;      \
            asm volatile("cp.async.cg.shared.global [%0], [%1], 16;\n"       \
                         :: "r"(dst), "l"(src));                             \
        }                                                                    \
        asm volatile("cp.async.commit_group;\n");                            \
    } while (0)

    ISSUE_STAGE(0, 0);

    for (int kslab = 0; kslab < NS; kslab++) {
        if (kslab + 1 < NS) {
            ISSUE_STAGE((kslab + 1) & 1, (kslab + 1) << 5);
            asm volatile("cp.async.wait_group 1;\n");
        } else {
            asm volatile("cp.async.wait_group 0;\n");
        }
        __syncthreads();

        const uint32_t stb = sbase + (kslab & 1) * (GS_STAGE * 4);

        #pragma unroll
        for (int ks = 0; ks < 2; ks++) {
            const uint32_t kb = (uint32_t)(ks * 32);   // 8 words = 32 bytes
            uint32_t ah[4][4], al[4][4], bh[4][2], bl[4][2];
            #pragma unroll
            for (int mf = 0; mf < 4; mf++) {
                ldsm4(ah[mf][0], ah[mf][1], ah[mf][2], ah[mf][3],
                      stb + aoffs[mf] + kb);
                ldsm4(al[mf][0], al[mf][1], al[mf][2], al[mf][3],
                      stb + (uint32_t)(GS_ARR * 4) + aoffs[mf] + kb);
            }
            #pragma unroll
            for (int p = 0; p < 2; p++) {
                ldsm4(bh[p*2][0], bh[p*2][1], bh[p*2+1][0], bh[p*2+1][1],
                      stb + (uint32_t)(2 * GS_ARR * 4) + boffs[p] + kb);
                ldsm4(bl[p*2][0], bl[p*2][1], bl[p*2+1][0], bl[p*2+1][1],
                      stb + (uint32_t)(3 * GS_ARR * 4) + boffs[p] + kb);
            }
            #pragma unroll
            for (int mf = 0; mf < 4; mf++)
                #pragma unroll
                for (int nf = 0; nf < 4; nf++) {
                    mma16816(acc[mf][nf], ah[mf][0], ah[mf][1], ah[mf][2], ah[mf][3],
                             bh[nf][0], bh[nf][1]);
                    mma16816(acc[mf][nf], ah[mf][0], ah[mf][1], ah[mf][2], ah[mf][3],
                             bl[nf][0], bl[nf][1]);
                    mma16816(acc[mf][nf], al[mf][0], al[mf][1], al[mf][2], al[mf][3],
                             bh[nf][0], bh[nf][1]);
                }
        }
        __syncthreads();
    }
    #undef ISSUE_STAGE

    // epilogue
    #pragma unroll
    for (int mf = 0; mf < 4; mf++) {
        #pragma unroll
        for (int nf = 0; nf < 4; nf++) {
            int row = row0 + wm * 64 + mf * 16 + lq;
            int col = col0 + wn * 32 + nf * 8 + lr * 2;
            #pragma unroll
            for (int half = 0; half < 2; half++) {
                int rr = row + half * 8;
                float v0 = acc[mf][nf][half * 2 + 0];
                float v1 = acc[mf][nf][half * 2 + 1];
                if (EPI == 1) {
                    v0 += bias[col];     v1 += bias[col + 1];
                    v0 = 0.5f * v0 * (1.f + erff(v0 * 0.70710678118654752f));
                    v1 = 0.5f * v1 * (1.f + erff(v1 * 0.70710678118654752f));
                } else if (EPI == 2) {
                    v0 += bias[col]     + res[(size_t)rr * N + col];
                    v1 += bias[col + 1] + res[(size_t)rr * N + col + 1];
                }
                *(float2*)(C + (size_t)rr * N + col) = make_float2(v0, v1);
            }
        }
    }
}

// ---------------- differential flash attention (register-tiled) ----------------
extern __shared__ float sm_attn[];
#define PS 68

__global__ __launch_bounds__(256) void attn_kernel(
    const float* __restrict__ q, const float* __restrict__ k, const float* __restrict__ v,
    const float* __restrict__ lq1, const float* __restrict__ lk1,
    const float* __restrict__ lq2, const float* __restrict__ lk2,
    const float* __restrict__ subw, uint32_t* __restrict__ aoh, uint32_t* __restrict__ aol)
{
    float* sQ0 = sm_attn;
    float* sQ1 = sQ0 + 32*PS;
    float* sK0 = sQ1 + 32*PS;
    float* sK1 = sK0 + 32*PS;
    float* sS0 = sK1 + 32*PS;
    float* sS1 = sS0 + 64*PS;
    float* sV  = sS1 + 64*PS;
    float* sF0 = sV  + 64*PS;
    float* sF1 = sF0 + 64;
    float* sL0 = sF1 + 64;
    float* sL1 = sL0 + 64;
    __shared__ float s_lam;

    const int tid = threadIdx.x;
    const int qt = blockIdx.x, h = blockIdx.y, b = blockIdx.z;

    if (tid == 0) {
        float s1 = 0.f, s2 = 0.f;
        #pragma unroll
        for (int i = 0; i < HD; i++) { s1 += lq1[i]*lk1[i]; s2 += lq2[i]*lk2[i]; }
        s_lam = expf(s1) - expf(s2) + LAMBDA_INIT;
    }

    const float scale = 0.17677669529663687f * 1.4426950408889634f;

    #pragma unroll
    for (int e = 0; e < 4; e++) {
        int lin = tid + e * 256;
        int head = lin >> 9;
        int rem = lin & 511;
        int row = rem >> 3;
        int c4 = (rem & 7) << 2;
        float4 qv = *(const float4*)(q + ((size_t)(b*SEQ + qt*64 + row))*EMBED + (2*h + head)*HD + c4);
        float* dst = head ? sQ1 : sQ0;
        dst[(c4+0)*PS + row] = qv.x*scale;
        dst[(c4+1)*PS + row] = qv.y*scale;
        dst[(c4+2)*PS + row] = qv.z*scale;
        dst[(c4+3)*PS + row] = qv.w*scale;
    }

    const int ty = tid >> 4, tx = tid & 15;
    const int sr = tid >> 2, spart = tid & 3;

    float m0 = -1e30f, m1 = -1e30f, l0 = 0.f, l1 = 0.f;
    float acc0[4][4], acc1[4][4];
    #pragma unroll
    for (int i = 0; i < 4; i++)
        #pragma unroll
        for (int j = 0; j < 4; j++) { acc0[i][j] = 0.f; acc1[i][j] = 0.f; }

    for (int kt = 0; kt < SEQ/64; kt++) {
        __syncthreads();
        #pragma unroll
        for (int e = 0; e < 4; e++) {
            int lin = tid + e * 256;
            int head = lin >> 9;
            int rem = lin & 511;
            int row = rem >> 3;
            int c4 = (rem & 7) << 2;
            float4 kv = *(const float4*)(k + ((size_t)(b*SEQ + kt*64 + row))*EMBED + (2*h + head)*HD + c4);
            float* dst = head ? sK1 : sK0;
            dst[(c4+0)*PS + row] = kv.x;
            dst[(c4+1)*PS + row] = kv.y;
            dst[(c4+2)*PS + row] = kv.z;
            dst[(c4+3)*PS + row] = kv.w;
        }
        #pragma unroll
        for (int e = 0; e < 4; e++) {
            int lin = tid + e * 256;
            int row = lin >> 4;
            int c4 = (lin & 15) << 2;
            float4 vv = *(const float4*)(v + ((size_t)(b*SEQ + kt*64 + row))*EMBED + h*VD + c4);
            *(float4*)(sV + row*PS + c4) = vv;
        }
        __syncthreads();

        {
            float s0a[4][4], s1a[4][4];
            #pragma unroll
            for (int i = 0; i < 4; i++)
                #pragma unroll
                for (int j = 0; j < 4; j++) { s0a[i][j] = 0.f; s1a[i][j] = 0.f; }
            #pragma unroll 8
            for (int kk = 0; kk < 32; kk++) {
                float4 a0 = *(const float4*)(sQ0 + kk*PS + ty*4);
                float4 a1 = *(const float4*)(sQ1 + kk*PS + ty*4);
                float4 b0 = *(const float4*)(sK0 + kk*PS + tx*4);
                float4 b1 = *(const float4*)(sK1 + kk*PS + tx*4);
                float aa0[4] = {a0.x,a0.y,a0.z,a0.w};
                float aa1[4] = {a1.x,a1.y,a1.z,a1.w};
                float bb0[4] = {b0.x,b0.y,b0.z,b0.w};
                float bb1[4] = {b1.x,b1.y,b1.z,b1.w};
                #pragma unroll
                for (int i = 0; i < 4; i++)
                    #pragma unroll
                    for (int j = 0; j < 4; j++) {
                        s0a[i][j] += aa0[i]*bb0[j];
                        s1a[i][j] += aa1[i]*bb1[j];
                    }
            }
            #pragma unroll
            for (int i = 0; i < 4; i++)
                #pragma unroll
                for (int j = 0; j < 4; j++) {
                    sS0[(ty*4+i)*PS + tx*4+j] = s0a[i][j];
                    sS1[(ty*4+i)*PS + tx*4+j] = s1a[i][j];
                }
        }
        __syncthreads();

        {
            float v0[16], v1[16];
            float tm0 = -1e30f, tm1 = -1e30f;
            #pragma unroll
            for (int c4 = 0; c4 < 4; c4++) {
                float4 f0 = *(const float4*)(sS0 + sr*PS + spart*16 + c4*4);
                float4 f1 = *(const float4*)(sS1 + sr*PS + spart*16 + c4*4);
                v0[c4*4+0]=f0.x; v0[c4*4+1]=f0.y; v0[c4*4+2]=f0.z; v0[c4*4+3]=f0.w;
                v1[c4*4+0]=f1.x; v1[c4*4+1]=f1.y; v1[c4*4+2]=f1.z; v1[c4*4+3]=f1.w;
                tm0 = fmaxf(tm0, fmaxf(fmaxf(f0.x,f0.y), fmaxf(f0.z,f0.w)));
                tm1 = fmaxf(tm1, fmaxf(fmaxf(f1.x,f1.y), fmaxf(f1.z,f1.w)));
            }
            #pragma unroll
            for (int o = 1; o < 4; o <<= 1) {
                tm0 = fmaxf(tm0, __shfl_xor_sync(0xffffffffu, tm0, o));
                tm1 = fmaxf(tm1, __shfl_xor_sync(0xffffffffu, tm1, o));
            }
            const float nm0 = fmaxf(m0, tm0), nm1 = fmaxf(m1, tm1);
            const float f0 = exp2f(m0 - nm0), f1 = exp2f(m1 - nm1);
            float ps0 = 0.f, ps1 = 0.f;
            #pragma unroll
            for (int c = 0; c < 16; c++) {
                v0[c] = exp2f(v0[c] - nm0);
                v1[c] = exp2f(v1[c] - nm1);
                ps0 += v0[c]; ps1 += v1[c];
            }
            #pragma unroll
            for (int c4 = 0; c4 < 4; c4++) {
                *(float4*)(sS0 + sr*PS + spart*16 + c4*4) =
                    make_float4(v0[c4*4+0], v0[c4*4+1], v0[c4*4+2], v0[c4*4+3]);
                *(float4*)(sS1 + sr*PS + spart*16 + c4*4) =
                    make_float4(v1[c4*4+0], v1[c4*4+1], v1[c4*4+2], v1[c4*4+3]);
            }
            #pragma unroll
            for (int o = 1; o < 4; o <<= 1) {
                ps0 += __shfl_xor_sync(0xffffffffu, ps0, o);
                ps1 += __shfl_xor_sync(0xffffffffu, ps1, o);
            }
            l0 = l0 * f0 + ps0; l1 = l1 * f1 + ps1;
            m0 = nm0; m1 = nm1;
            if (spart == 0) {
                sF0[sr] = f0; sF1[sr] = f1;
                sL0[sr] = l0; sL1[sr] = l1;
            }
        }
        __syncthreads();

        {
            float f0r[4], f1r[4];
            #pragma unroll
            for (int i = 0; i < 4; i++) { f0r[i] = sF0[ty*4+i]; f1r[i] = sF1[ty*4+i]; }
            #pragma unroll
            for (int i = 0; i < 4; i++)
                #pragma unroll
                for (int j = 0; j < 4; j++) { acc0[i][j] *= f0r[i]; acc1[i][j] *= f1r[i]; }
            #pragma unroll 8
            for (int jk = 0; jk < 64; jk++) {
                float4 vv = *(const float4*)(sV + jk*PS + tx*4);
                float vva[4] = {vv.x, vv.y, vv.z, vv.w};
                float p0[4], p1[4];
                #pragma unroll
                for (int i = 0; i < 4; i++) {
                    p0[i] = sS0[(ty*4+i)*PS + jk];
                    p1[i] = sS1[(ty*4+i)*PS + jk];
                }
                #pragma unroll
                for (int i = 0; i < 4; i++)
                    #pragma unroll
                    for (int j = 0; j < 4; j++) {
                        acc0[i][j] += p0[i]*vva[j];
                        acc1[i][j] += p1[i]*vva[j];
                    }
            }
        }
    }

    // epilogue: combine, rmsnorm(64), write bf16 hi/lo
    const float lam = s_lam;
    float linv0[4], linv1[4];
    #pragma unroll
    for (int i = 0; i < 4; i++) {
        linv0[i] = 1.f / sL0[ty*4+i];
        linv1[i] = 1.f / sL1[ty*4+i];
    }
    float o[4][4], ss[4];
    #pragma unroll
    for (int i = 0; i < 4; i++) {
        ss[i] = 0.f;
        #pragma unroll
        for (int j = 0; j < 4; j++) {
            o[i][j] = acc0[i][j]*linv0[i] - lam*acc1[i][j]*linv1[i];
            ss[i] += o[i][j]*o[i][j];
        }
    }
    #pragma unroll
    for (int i = 0; i < 4; i++)
        #pragma unroll
        for (int off = 1; off < 16; off <<= 1)
            ss[i] += __shfl_xor_sync(0xffffffffu, ss[i], off);
    float4 wv = *(const float4*)(subw + tx*4);
    float wva[4] = {wv.x, wv.y, wv.z, wv.w};
    #pragma unroll
    for (int i = 0; i < 4; i++) {
        const float rsn = rsqrtf(ss[i] * (1.f / VD) + EPS_LN) * (1.f - LAMBDA_INIT);
        float o0 = o[i][0]*rsn*wva[0];
        float o1 = o[i][1]*rsn*wva[1];
        float o2 = o[i][2]*rsn*wva[2];
        float o3 = o[i][3]*rsn*wva[3];
        uint32_t h0, l0u, h1, l1u;
        split2(o0, o1, h0, l0u);
        split2(o2, o3, h1, l1u);
        size_t u = (((size_t)(b*SEQ + qt*64 + ty*4 + i))*EMBED + h*VD + tx*4) >> 1;
        aoh[u] = h0; aoh[u+1] = h1;
        aol[u] = l0u; aol[u+1] = l1u;
    }
}

#define ATTN_SMEM ((4*32*PS + 2*64*PS + 64*PS + 4*64) * (int)sizeof(float))

// ---------------- host launch ----------------
extern "C" void kernel_launch(void* const* d_in, const int* in_sizes, int n_in,
                              void* d_out, int out_size)
{
    (void)in_sizes; (void)n_in; (void)out_size;
    const float* x     = (const float*)d_in[0];
    const float* Wq    = (const float*)d_in[1];
    const float* Wk    = (const float*)d_in[2];
    const float* Wv    = (const float*)d_in[3];
    const float* Wo    = (const float*)d_in[4];
    const float* lq1   = (const float*)d_in[5];
    const float* lk1   = (const float*)d_in[6];
    const float* lq2   = (const float*)d_in[7];
    const float* lk2   = (const float*)d_in[8];
    const float* subw  = (const float*)d_in[9];
    const float* n1w   = (const float*)d_in[10];
    const float* n1b   = (const float*)d_in[11];
    const float* n2w   = (const float*)d_in[12];
    const float* n2b   = (const float*)d_in[13];
    const float* mln1w = (const float*)d_in[14];
    const float* mln1b = (const float*)d_in[15];
    const float* mW1   = (const float*)d_in[16];
    const float* mb1   = (const float*)d_in[17];
    const float* mln2w = (const float*)d_in[18];
    const float* mln2b = (const float*)d_in[19];
    const float* mW2   = (const float*)d_in[20];
    const float* mb2   = (const float*)d_in[21];
    float* out = (float*)d_out;

    float *qb, *kb, *vb, *ab, *hb, *z1;
    uint32_t *xnh, *xnl, *aoh, *aol, *z2h, *z2l;
    uint32_t *wqh, *wql, *wkh, *wkl, *wvh, *wvl, *woh, *wol, *w1h, *w1l, *w2h, *w2l;
    cudaGetSymbolAddress((void**)&qb, g_q);
    cudaGetSymbolAddress((void**)&kb, g_k);
    cudaGetSymbolAddress((void**)&vb, g_v);
    cudaGetSymbolAddress((void**)&ab, g_ab);
    cudaGetSymbolAddress((void**)&hb, g_h);
    cudaGetSymbolAddress((void**)&z1, g_z1);
    cudaGetSymbolAddress((void**)&xnh, g_xnh);
    cudaGetSymbolAddress((void**)&xnl, g_xnl);
    cudaGetSymbolAddress((void**)&aoh, g_aoh);
    cudaGetSymbolAddress((void**)&aol, g_aol);
    cudaGetSymbolAddress((void**)&z2h, g_z2h);
    cudaGetSymbolAddress((void**)&z2l, g_z2l);
    cudaGetSymbolAddress((void**)&wqh, g_wqh);
    cudaGetSymbolAddress((void**)&wql, g_wql);
    cudaGetSymbolAddress((void**)&wkh, g_wkh);
    cudaGetSymbolAddress((void**)&wkl, g_wkl);
    cudaGetSymbolAddress((void**)&wvh, g_wvh);
    cudaGetSymbolAddress((void**)&wvl, g_wvl);
    cudaGetSymbolAddress((void**)&woh, g_woh);
    cudaGetSymbolAddress((void**)&wol, g_wol);
    cudaGetSymbolAddress((void**)&w1h, g_w1h);
    cudaGetSymbolAddress((void**)&w1l, g_w1l);
    cudaGetSymbolAddress((void**)&w2h, g_w2h);
    cudaGetSymbolAddress((void**)&w2l, g_w2l);

    static bool attr_set = false;
    if (!attr_set) {
        cudaFuncSetAttribute(attn_kernel,
            cudaFuncAttributeMaxDynamicSharedMemorySize, ATTN_SMEM);
        cudaFuncSetAttribute(bf_gemm<0>,
            cudaFuncAttributeMaxDynamicSharedMemorySize, GEMM_SMEM);
        cudaFuncSetAttribute(bf_gemm<1>,
            cudaFuncAttributeMaxDynamicSharedMemorySize, GEMM_SMEM);
        cudaFuncSetAttribute(bf_gemm<2>,
            cudaFuncAttributeMaxDynamicSharedMemorySize, GEMM_SMEM);
        attr_set = true;
    }

    // 0. split all weights in ONE launch (grid.y selects weight)
    const int nw = EMBED*EMBED/2, nm = EXPD*EMBED/2;
    {
        dim3 gs((nm + 255) / 256, 6);
        split_all<<<gs, 256>>>(
            (const float2*)Wq,  wqh, wql, nw,
            (const float2*)Wk,  wkh, wkl, nw,
            (const float2*)Wv,  wvh, wvl, nw,
            (const float2*)Wo,  woh, wol, nw,
            (const float2*)mW1, w1h, w1l, nm,
            (const float2*)mW2, w2h, w2l, nm);
    }

    const dim3 g512(EMBED/128, BN/128);   // (4, 64)
    const dim3 g2048(EXPD/128, BN/128);   // (16, 64)

    // 1. xn = LN(x) -> bf16 hi/lo
    ln_split<EMBED><<<BN, 128>>>(x, n1w, n1b, xnh, xnl);
    // 2. q/k/v = xn @ W^T
    bf_gemm<0><<<g512, 256, GEMM_SMEM>>>(xnh, xnl, wqh, wql, nullptr, nullptr, qb, BN, EMBED, EMBED);
    bf_gemm<0><<<g512, 256, GEMM_SMEM>>>(xnh, xnl, wkh, wkl, nullptr, nullptr, kb, BN, EMBED, EMBED);
    bf_gemm<0><<<g512, 256, GEMM_SMEM>>>(xnh, xnl, wvh, wvl, nullptr, nullptr, vb, BN, EMBED, EMBED);
    // 3. differential attention -> ao bf16 hi/lo   (launch #5 -> ncu capture)
    attn_kernel<<<dim3(SEQ/64, HEADS, BATCH), 256, ATTN_SMEM>>>(
        qb, kb, vb, lq1, lk1, lq2, lk2, subw, aoh, aol);
    // 4. a = ao @ Wo^T (fp32)
    bf_gemm<0><<<g512, 256, GEMM_SMEM>>>(aoh, aol, woh, wol, nullptr, nullptr, ab, BN, EMBED, EMBED);
    // 5. h = LN(a)+x (fp32) ; z = LN(h) (bf16 hi/lo)
    hz_kernel<<<BN, 128>>>(ab, x, n2w, n2b, mln1w, mln1b, hb, xnh, xnl);
    // 6. z1 = GELU(z @ mW1^T + mb1) (fp32)
    bf_gemm<1><<<g2048, 256, GEMM_SMEM>>>(xnh, xnl, w1h, w1l, mb1, nullptr, z1, BN, EXPD, EMBED);
    // 7. z2 = LN(z1) -> bf16 hi/lo
    ln_split<EXPD><<<BN, 128>>>(z1, mln2w, mln2b, z2h, z2l);
    // 8. out = z2 @ mW2^T + mb2 + h
    bf_gemm<2><<<g512, 256, GEMM_SMEM>>>(z2h, z2l, w2h, w2l, mb2, hb, out, BN, EMBED, EXPD);
}